// round 1
// baseline (speedup 1.0000x reference)
#include <cuda_runtime.h>

#define NB 4
#define NC 64
#define NH 128
#define NW 128
#define NWIN 31
#define NL (NWIN*NWIN)

// scratch (allocation-free rule: __device__ globals)
__device__ float g_acc_l[NB*NC*NH*NW];
__device__ float g_acc_h[NB*NC*NH*NW];
__device__ float g_mean[NB*NC];
__device__ float g_sgate[NB*NC];

// ---------------- SE: per-channel global mean ----------------
__global__ void mean_kernel(const float* __restrict__ high) {
    int bc = blockIdx.x; // b*64 + c
    const float* p = high + (size_t)bc * (NH*NW);
    float s = 0.f;
    for (int i = threadIdx.x; i < NH*NW; i += 256) s += p[i];
    __shared__ float red[256];
    red[threadIdx.x] = s; __syncthreads();
    for (int k = 128; k > 0; k >>= 1) {
        if (threadIdx.x < k) red[threadIdx.x] += red[threadIdx.x + k];
        __syncthreads();
    }
    if (threadIdx.x == 0) g_mean[bc] = red[0] * (1.f/(NH*NW));
}

// ---------------- SE: gate per (b,c) ----------------
__global__ void se_kernel(const float* __restrict__ w10, const float* __restrict__ w20,
                          const float* __restrict__ w11, const float* __restrict__ w21,
                          const float* __restrict__ w12, const float* __restrict__ w22) {
    int t = threadIdx.x;               // 0..255 = b*64+c
    int b = t >> 6, c = t & 63;
    int g  = (c < 22) ? 0 : ((c < 43) ? 1 : 2);
    int of = (g == 0) ? 0 : ((g == 1) ? 22 : 43);
    int gc = (g == 0) ? 22 : 21;
    const float* w1 = (g==0) ? w10 : ((g==1) ? w11 : w12);
    const float* w2 = (g==0) ? w20 : ((g==1) ? w21 : w22);
    float h = 0.f;
    for (int j = 0; j < gc; j++) h += g_mean[b*64 + of + j] * w1[j];
    h = fmaxf(h, 0.f);
    float v = h * w2[c - of];
    g_sgate[t] = 1.f / (1.f + __expf(-v));
}

// ---------------- main: per-window projections + bidirectional attention ----------------
// smem layout (floats): xl[4096] xh[4096] wb[3*4096] Y[6*4096]
// Y slots: 0=ql 1=kh 2=vh 3=qh 4=kl 5=vl
__global__ void __launch_bounds__(256) attn_kernel(
    const float* __restrict__ low, const float* __restrict__ high,
    const float* __restrict__ w_ql, const float* __restrict__ w_kh,
    const float* __restrict__ w_vh, const float* __restrict__ w_qh,
    const float* __restrict__ w_kl, const float* __restrict__ w_vl)
{
    extern __shared__ float sm[];
    float* xl = sm;
    float* xh = sm + 4096;
    float* wb = sm + 8192;     // 3 weights staged
    float* Y  = sm + 20480;    // 6 * 4096

    int t = threadIdx.x;
    int l = blockIdx.x, b = blockIdx.y;
    int y0 = (l / NWIN) * 4, x0 = (l % NWIN) * 4;

    // load both windows (apply SE gate to high)
    for (int i = t; i < 4096; i += 256) {
        int c = i >> 6, n = i & 63;
        int r = n >> 3, cc = n & 7;
        size_t gi = (((size_t)(b*NC + c))*NH + (y0 + r))*NW + (x0 + cc);
        xl[i] = low[gi];
        xh[i] = high[gi] * g_sgate[b*64 + c];
    }

    int ot = (t >> 4) << 2;     // o tile base (0..60)
    int nb = (t & 15) << 2;     // n tile base (0..60)

    // two groups: g=0: X=xl, W={ql,kl,vl}->slots{0,4,5}; g=1: X=xh, W={kh,vh,qh}->slots{1,2,3}
    for (int g = 0; g < 2; g++) {
        __syncthreads();  // xl/xh ready (g=0); prev Y done before wb overwrite (g=1)
        const float* W0 = g ? w_kh : w_ql;
        const float* W1 = g ? w_vh : w_kl;
        const float* W2 = g ? w_qh : w_vl;
        for (int i = t; i < 12288; i += 256) {
            int p = i >> 12;
            const float* Wp = (p == 0) ? W0 : ((p == 1) ? W1 : W2);
            wb[i] = Wp[i & 4095];
        }
        __syncthreads();
        const float* Xs = g ? xh : xl;

        float acc[3][16];
        #pragma unroll
        for (int p = 0; p < 3; p++)
            #pragma unroll
            for (int j = 0; j < 16; j++) acc[p][j] = 0.f;

        #pragma unroll 4
        for (int c0 = 0; c0 < 64; c0 += 4) {
            float4 xr0 = *(const float4*)(Xs + (c0+0)*64 + nb);
            float4 xr1 = *(const float4*)(Xs + (c0+1)*64 + nb);
            float4 xr2 = *(const float4*)(Xs + (c0+2)*64 + nb);
            float4 xr3 = *(const float4*)(Xs + (c0+3)*64 + nb);
            #pragma unroll
            for (int p = 0; p < 3; p++) {
                #pragma unroll
                for (int i = 0; i < 4; i++) {
                    float4 wr = *(const float4*)(wb + p*4096 + (ot+i)*64 + c0);
                    acc[p][i*4+0] += wr.x*xr0.x + wr.y*xr1.x + wr.z*xr2.x + wr.w*xr3.x;
                    acc[p][i*4+1] += wr.x*xr0.y + wr.y*xr1.y + wr.z*xr2.y + wr.w*xr3.y;
                    acc[p][i*4+2] += wr.x*xr0.z + wr.y*xr1.z + wr.z*xr2.z + wr.w*xr3.z;
                    acc[p][i*4+3] += wr.x*xr0.w + wr.y*xr1.w + wr.z*xr2.w + wr.w*xr3.w;
                }
            }
        }
        float* Y0 = Y + (g ? 1 : 0)*4096;
        float* Y1 = Y + (g ? 2 : 4)*4096;
        float* Y2 = Y + (g ? 3 : 5)*4096;
        #pragma unroll
        for (int i = 0; i < 4; i++)
            #pragma unroll
            for (int j = 0; j < 4; j++) {
                Y0[(ot+i)*64 + nb + j] = acc[0][i*4+j];
                Y1[(ot+i)*64 + nb + j] = acc[1][i*4+j];
                Y2[(ot+i)*64 + nb + j] = acc[2][i*4+j];
            }
    }
    __syncthreads();

    const float* yql = Y;
    const float* ykh = Y + 4096;
    const float* yvh = Y + 8192;
    const float* yqh = Y + 12288;
    const float* ykl = Y + 16384;
    const float* yvl = Y + 20480;

    int h = t >> 6, n = t & 63;
    int r = n >> 3, cc = n & 7;
    size_t pix = (size_t)(y0 + r)*NW + (x0 + cc);

    // ---- direction 1: a_lh = softmax(q_l . k_h), ol = a_lh . v_h -> acc_l ----
    {
        float q[16];
        #pragma unroll
        for (int dd = 0; dd < 16; dd++) q[dd] = yql[(h*16+dd)*64 + n];
        float lg[64];
        #pragma unroll
        for (int m = 0; m < 64; m++) {
            float s = 0.f;
            #pragma unroll
            for (int dd = 0; dd < 16; dd++) s += q[dd] * ykh[(h*16+dd)*64 + m];
            lg[m] = s * 0.25f;
        }
        float mx = lg[0];
        #pragma unroll
        for (int m = 1; m < 64; m++) mx = fmaxf(mx, lg[m]);
        float ssum = 0.f;
        #pragma unroll
        for (int m = 0; m < 64; m++) { lg[m] = __expf(lg[m] - mx); ssum += lg[m]; }
        float inv = 1.f / ssum;
        float oa[16];
        #pragma unroll
        for (int dd = 0; dd < 16; dd++) oa[dd] = 0.f;
        #pragma unroll
        for (int m = 0; m < 64; m++) {
            float a = lg[m];
            #pragma unroll
            for (int dd = 0; dd < 16; dd++) oa[dd] += a * yvh[(h*16+dd)*64 + m];
        }
        #pragma unroll
        for (int dd = 0; dd < 16; dd++) {
            int c = h*16 + dd;
            atomicAdd(&g_acc_l[((size_t)(b*NC + c))*(NH*NW) + pix], oa[dd]*inv);
        }
    }
    // ---- direction 2: a_hl = softmax(q_h . k_l), oh = a_hl . v_l -> acc_h ----
    {
        float q[16];
        #pragma unroll
        for (int dd = 0; dd < 16; dd++) q[dd] = yqh[(h*16+dd)*64 + n];
        float lg[64];
        #pragma unroll
        for (int m = 0; m < 64; m++) {
            float s = 0.f;
            #pragma unroll
            for (int dd = 0; dd < 16; dd++) s += q[dd] * ykl[(h*16+dd)*64 + m];
            lg[m] = s * 0.25f;
        }
        float mx = lg[0];
        #pragma unroll
        for (int m = 1; m < 64; m++) mx = fmaxf(mx, lg[m]);
        float ssum = 0.f;
        #pragma unroll
        for (int m = 0; m < 64; m++) { lg[m] = __expf(lg[m] - mx); ssum += lg[m]; }
        float inv = 1.f / ssum;
        float oa[16];
        #pragma unroll
        for (int dd = 0; dd < 16; dd++) oa[dd] = 0.f;
        #pragma unroll
        for (int m = 0; m < 64; m++) {
            float a = lg[m];
            #pragma unroll
            for (int dd = 0; dd < 16; dd++) oa[dd] += a * yvl[(h*16+dd)*64 + m];
        }
        #pragma unroll
        for (int dd = 0; dd < 16; dd++) {
            int c = h*16 + dd;
            atomicAdd(&g_acc_h[((size_t)(b*NC + c))*(NH*NW) + pix], oa[dd]*inv);
        }
    }
}

// ---------------- epilogue: divide by overlap count, 1x1 proj + residual ----------------
__device__ __forceinline__ int covdim(int y) {
    int imin = (y >= 8) ? ((y - 4) >> 2) : 0;
    int imax = y >> 2; if (imax > 30) imax = 30;
    return imax - imin + 1;
}

__global__ void __launch_bounds__(256) epi_kernel(
    const float* __restrict__ low, const float* __restrict__ high,
    const float* __restrict__ wpl, const float* __restrict__ wph,
    float* __restrict__ out)
{
    extern __shared__ float sm[];
    float* tl = sm;                 // 8192
    float* th = sm + 8192;          // 8192
    float* wl = sm + 16384;         // 64*65 transposed, padded
    float* wh = sm + 16384 + 4160;  // 64*65

    int t = threadIdx.x;
    int y = blockIdx.x, b = blockIdx.y;
    float cy = (float)covdim(y);

    for (int i = t; i < 8192; i += 256) {
        int c = i >> 7, x = i & 127;
        float ic = 1.f / (cy * (float)covdim(x));
        size_t gi = (((size_t)(b*NC + c))*NH + y)*NW + x;
        tl[i] = g_acc_l[gi] * ic;
        th[i] = g_acc_h[gi] * ic;
    }
    for (int i = t; i < 4096; i += 256) {
        int o = i >> 6, c = i & 63;
        wl[c*65 + o] = wpl[i];
        wh[c*65 + o] = wph[i];
    }
    __syncthreads();

    int x = t & 127, og = (t >> 7) * 32;
    float rl[32], rh[32];
    #pragma unroll
    for (int o = 0; o < 32; o++) { rl[o] = 0.f; rh[o] = 0.f; }
    for (int c = 0; c < 64; c++) {
        float tv = tl[c*128 + x];
        float hv = th[c*128 + x];
        #pragma unroll
        for (int o = 0; o < 32; o++) {
            rl[o] += wl[c*65 + og + o] * tv;
            rh[o] += wh[c*65 + og + o] * hv;
        }
    }
    size_t half = (size_t)NB*NC*NH*NW;
    #pragma unroll
    for (int o = 0; o < 32; o++) {
        size_t gi = (((size_t)(b*NC + og + o))*NH + y)*NW + x;
        out[gi]        = low[gi]  + rl[o];
        out[half + gi] = high[gi] + rh[o];
    }
}

extern "C" void kernel_launch(void* const* d_in, const int* in_sizes, int n_in,
                              void* d_out, int out_size)
{
    (void)in_sizes; (void)n_in; (void)out_size;
    const float* low  = (const float*)d_in[0];
    const float* high = (const float*)d_in[1];
    const float* w_ql = (const float*)d_in[2];
    const float* w_kh = (const float*)d_in[3];
    const float* w_vh = (const float*)d_in[4];
    const float* w_qh = (const float*)d_in[5];
    const float* w_kl = (const float*)d_in[6];
    const float* w_vl = (const float*)d_in[7];
    const float* wpl  = (const float*)d_in[8];
    const float* wph  = (const float*)d_in[9];

    void* pl; cudaGetSymbolAddress(&pl, g_acc_l);
    void* ph; cudaGetSymbolAddress(&ph, g_acc_h);
    cudaMemsetAsync(pl, 0, sizeof(float)*(size_t)NB*NC*NH*NW);
    cudaMemsetAsync(ph, 0, sizeof(float)*(size_t)NB*NC*NH*NW);

    cudaFuncSetAttribute(attn_kernel, cudaFuncAttributeMaxDynamicSharedMemorySize, 45056*4);
    cudaFuncSetAttribute(epi_kernel,  cudaFuncAttributeMaxDynamicSharedMemorySize, 24704*4);

    mean_kernel<<<NB*NC, 256>>>(high);
    se_kernel<<<1, 256>>>((const float*)d_in[10], (const float*)d_in[11],
                          (const float*)d_in[12], (const float*)d_in[13],
                          (const float*)d_in[14], (const float*)d_in[15]);
    attn_kernel<<<dim3(NL, NB), 256, 45056*4>>>(low, high, w_ql, w_kh, w_vh, w_qh, w_kl, w_vl);
    epi_kernel<<<dim3(NH, NB), 256, 24704*4>>>(low, high, wpl, wph, (float*)d_out);
}

// round 2
// speedup vs baseline: 2.0070x; 2.0070x over previous
#include <cuda_runtime.h>

#define NB 4
#define NC 64
#define NH 128
#define NW 128
#define NPIX (NH*NW)
#define NWIN 31
#define NL (NWIN*NWIN)

// proj order: 0=ql 1=kh 2=vh 3=qh 4=kl 5=vl
__device__ float g_proj[6*NB*NC*NPIX];
__device__ float g_acc_l[NB*NC*NPIX];
__device__ float g_acc_h[NB*NC*NPIX];
__device__ float g_mean[NB*NC];
__device__ float g_sgate[NB*NC];

// ---------------- packed f32x2 helpers ----------------
__device__ __forceinline__ unsigned long long pk2(float lo, float hi) {
    unsigned long long r;
    asm("mov.b64 %0,{%1,%2};" : "=l"(r) : "f"(lo), "f"(hi));
    return r;
}
__device__ __forceinline__ void upk2(float& lo, float& hi, unsigned long long v) {
    asm("mov.b64 {%0,%1},%2;" : "=f"(lo), "=f"(hi) : "l"(v));
}
__device__ __forceinline__ unsigned long long fma2(unsigned long long a,
                                                   unsigned long long b,
                                                   unsigned long long c) {
    unsigned long long d;
    asm("fma.rn.f32x2 %0,%1,%2,%3;" : "=l"(d) : "l"(a), "l"(b), "l"(c));
    return d;
}

// ---------------- SE: per-channel global mean ----------------
__global__ void mean_kernel(const float* __restrict__ high) {
    int bc = blockIdx.x;
    const float* p = high + (size_t)bc * NPIX;
    float s = 0.f;
    for (int i = threadIdx.x; i < NPIX; i += 256) s += p[i];
    __shared__ float red[256];
    red[threadIdx.x] = s; __syncthreads();
    for (int k = 128; k > 0; k >>= 1) {
        if (threadIdx.x < k) red[threadIdx.x] += red[threadIdx.x + k];
        __syncthreads();
    }
    if (threadIdx.x == 0) g_mean[bc] = red[0] * (1.f/NPIX);
}

// ---------------- SE: gate per (b,c) ----------------
__global__ void se_kernel(const float* __restrict__ w10, const float* __restrict__ w20,
                          const float* __restrict__ w11, const float* __restrict__ w21,
                          const float* __restrict__ w12, const float* __restrict__ w22) {
    int t = threadIdx.x;
    int b = t >> 6, c = t & 63;
    int g  = (c < 22) ? 0 : ((c < 43) ? 1 : 2);
    int of = (g == 0) ? 0 : ((g == 1) ? 22 : 43);
    int gc = (g == 0) ? 22 : 21;
    const float* w1 = (g==0) ? w10 : ((g==1) ? w11 : w12);
    const float* w2 = (g==0) ? w20 : ((g==1) ? w21 : w22);
    float h = 0.f;
    for (int j = 0; j < gc; j++) h += g_mean[b*64 + of + j] * w1[j];
    h = fmaxf(h, 0.f);
    float v = h * w2[c - of];
    g_sgate[t] = 1.f / (1.f + __expf(-v));
}

// ---------------- global projections: Y[p] = W[p] @ X, 6 projections ----------------
// grid (NPIX/64, NB); block handles 64 out-ch x 64 pixels for all 6 projections
__global__ void __launch_bounds__(256) proj_kernel(
    const float* __restrict__ low, const float* __restrict__ high,
    const float* __restrict__ w_ql, const float* __restrict__ w_kh,
    const float* __restrict__ w_vh, const float* __restrict__ w_qh,
    const float* __restrict__ w_kl, const float* __restrict__ w_vl)
{
    extern __shared__ float sm[];
    float* xl = sm;            // 4096
    float* xh = sm + 4096;     // 4096
    float* wb = sm + 8192;     // 3*4096

    int t = threadIdx.x;
    int pix0 = blockIdx.x * 64;
    int b = blockIdx.y;

    // load X tiles (vectorized, coalesced); apply SE gate to high
    for (int i4 = t; i4 < 1024; i4 += 256) {
        int c = i4 >> 4, pp = (i4 & 15) * 4;
        size_t gi = (size_t)(b*NC + c)*NPIX + pix0 + pp;
        float4 vl = *(const float4*)(low + gi);
        float4 vh = *(const float4*)(high + gi);
        float gt = g_sgate[b*64 + c];
        vh.x *= gt; vh.y *= gt; vh.z *= gt; vh.w *= gt;
        *(float4*)(xl + c*64 + pp) = vl;
        *(float4*)(xh + c*64 + pp) = vh;
    }

    int ot = (t >> 4) << 2;
    int nb = (t & 15) << 2;

    for (int g = 0; g < 2; g++) {
        __syncthreads();
        const float* W0 = g ? w_kh : w_ql;
        const float* W1 = g ? w_vh : w_kl;
        const float* W2 = g ? w_qh : w_vl;
        for (int i = t; i < 12288; i += 256) {
            int p = i >> 12;
            const float* Wp = (p == 0) ? W0 : ((p == 1) ? W1 : W2);
            wb[i] = Wp[i & 4095];
        }
        __syncthreads();
        const float* Xs = g ? xh : xl;

        float acc[3][16];
        #pragma unroll
        for (int p = 0; p < 3; p++)
            #pragma unroll
            for (int j = 0; j < 16; j++) acc[p][j] = 0.f;

        #pragma unroll 4
        for (int c0 = 0; c0 < 64; c0 += 4) {
            float4 xr0 = *(const float4*)(Xs + (c0+0)*64 + nb);
            float4 xr1 = *(const float4*)(Xs + (c0+1)*64 + nb);
            float4 xr2 = *(const float4*)(Xs + (c0+2)*64 + nb);
            float4 xr3 = *(const float4*)(Xs + (c0+3)*64 + nb);
            #pragma unroll
            for (int p = 0; p < 3; p++) {
                #pragma unroll
                for (int i = 0; i < 4; i++) {
                    float4 wr = *(const float4*)(wb + p*4096 + (ot+i)*64 + c0);
                    acc[p][i*4+0] += wr.x*xr0.x + wr.y*xr1.x + wr.z*xr2.x + wr.w*xr3.x;
                    acc[p][i*4+1] += wr.x*xr0.y + wr.y*xr1.y + wr.z*xr2.y + wr.w*xr3.y;
                    acc[p][i*4+2] += wr.x*xr0.z + wr.y*xr1.z + wr.z*xr2.z + wr.w*xr3.z;
                    acc[p][i*4+3] += wr.x*xr0.w + wr.y*xr1.w + wr.z*xr2.w + wr.w*xr3.w;
                }
            }
        }
        // write to global proj slots: g0 -> {0,4,5}, g1 -> {1,2,3}
        int p0 = g ? 1 : 0, p1 = g ? 2 : 4, p2 = g ? 3 : 5;
        #pragma unroll
        for (int i = 0; i < 4; i++) {
            size_t base = (size_t)(b*NC + ot + i)*NPIX + pix0 + nb;
            *(float4*)(g_proj + (size_t)p0*NB*NC*NPIX + base) = *(float4*)&acc[0][i*4];
            *(float4*)(g_proj + (size_t)p1*NB*NC*NPIX + base) = *(float4*)&acc[1][i*4];
            *(float4*)(g_proj + (size_t)p2*NB*NC*NPIX + base) = *(float4*)&acc[2][i*4];
        }
    }
}

// ---------------- attention per direction (helper) ----------------
__device__ __forceinline__ void attn_dir(
    const float* __restrict__ Q, const float* __restrict__ K, const float* __restrict__ V,
    float* __restrict__ gacc, int h, int n, size_t pixoff)
{
    unsigned long long lg2[32];
    #pragma unroll
    for (int j = 0; j < 32; j++) lg2[j] = 0ULL;

    const float* Kh = K + h*16*64;
    const float* Qh = Q + h*16*64;
    const float* Vh = V + h*16*64;

    #pragma unroll
    for (int dd = 0; dd < 16; dd++) {
        float q = Qh[dd*64 + n];
        unsigned long long q2 = pk2(q, q);
        const float* krow = Kh + dd*64;
        #pragma unroll
        for (int m4 = 0; m4 < 16; m4++) {
            float4 k4 = *(const float4*)(krow + m4*4);
            lg2[m4*2]   = fma2(q2, pk2(k4.x, k4.y), lg2[m4*2]);
            lg2[m4*2+1] = fma2(q2, pk2(k4.z, k4.w), lg2[m4*2+1]);
        }
    }
    // softmax over 64 (scale 0.25)
    float mx = -1e30f;
    #pragma unroll
    for (int j = 0; j < 32; j++) {
        float a, bb; upk2(a, bb, lg2[j]);
        a *= 0.25f; bb *= 0.25f;
        lg2[j] = pk2(a, bb);
        mx = fmaxf(mx, fmaxf(a, bb));
    }
    float ssum = 0.f;
    #pragma unroll
    for (int j = 0; j < 32; j++) {
        float a, bb; upk2(a, bb, lg2[j]);
        a = __expf(a - mx); bb = __expf(bb - mx);
        ssum += a + bb;
        lg2[j] = pk2(a, bb);
    }
    float inv = 1.f / ssum;

    unsigned long long acc2[16];
    #pragma unroll
    for (int dd = 0; dd < 16; dd++) acc2[dd] = 0ULL;
    #pragma unroll
    for (int dd = 0; dd < 16; dd++) {
        const float* vrow = Vh + dd*64;
        #pragma unroll
        for (int m4 = 0; m4 < 16; m4++) {
            float4 v4 = *(const float4*)(vrow + m4*4);
            acc2[dd] = fma2(lg2[m4*2],   pk2(v4.x, v4.y), acc2[dd]);
            acc2[dd] = fma2(lg2[m4*2+1], pk2(v4.z, v4.w), acc2[dd]);
        }
    }
    #pragma unroll
    for (int dd = 0; dd < 16; dd++) {
        float a, bb; upk2(a, bb, acc2[dd]);
        atomicAdd(gacc + (size_t)(h*16+dd)*NPIX + pixoff, (a + bb) * inv);
    }
}

// ---------------- attention kernel: reads projected tiles, folds via atomics ----------------
__global__ void __launch_bounds__(256, 2) attn_kernel()
{
    extern __shared__ float Y[];  // 6*4096

    int t = threadIdx.x;
    int l = blockIdx.x, b = blockIdx.y;
    int y0 = (l / NWIN) * 4, x0 = (l % NWIN) * 4;

    // load 6 projected tiles (float4)
    for (int i4 = t; i4 < 6144; i4 += 256) {
        int p = i4 >> 10, rem = i4 & 1023;
        int c = rem >> 4, q4 = rem & 15;
        int r = q4 >> 1, cc = (q4 & 1) * 4;
        size_t gi = ((size_t)p*NB*NC + (size_t)(b*NC + c))*NPIX + (size_t)(y0 + r)*NW + x0 + cc;
        *(float4*)(Y + p*4096 + c*64 + r*8 + cc) = *(const float4*)(g_proj + gi);
    }
    __syncthreads();

    int h = t >> 6, n = t & 63;
    int r = n >> 3, cc = n & 7;
    size_t pixoff = (size_t)(y0 + r)*NW + x0 + cc;
    float* accl = g_acc_l + (size_t)b*NC*NPIX;
    float* acch = g_acc_h + (size_t)b*NC*NPIX;

    // dir1: q_l . k_h -> v_h into acc_l;   dir2: q_h . k_l -> v_l into acc_h
    attn_dir(Y + 0*4096, Y + 1*4096, Y + 2*4096, accl, h, n, pixoff);
    attn_dir(Y + 3*4096, Y + 4*4096, Y + 5*4096, acch, h, n, pixoff);
}

// ---------------- epilogue: normalize fold, 1x1 proj + residual ----------------
__device__ __forceinline__ int covdim(int y) {
    int imin = (y >= 8) ? ((y - 4) >> 2) : 0;
    int imax = y >> 2; if (imax > 30) imax = 30;
    return imax - imin + 1;
}

#define WST 72   // padded transposed weight stride

__global__ void __launch_bounds__(256) epi_kernel(
    const float* __restrict__ low, const float* __restrict__ high,
    const float* __restrict__ wpl, const float* __restrict__ wph,
    float* __restrict__ out)
{
    extern __shared__ float sm[];
    float* tl = sm;                    // 8192
    float* th = sm + 8192;             // 8192
    float* wl = sm + 16384;            // 64*WST
    float* wh = sm + 16384 + 64*WST;   // 64*WST

    int t = threadIdx.x;
    int y = blockIdx.x, b = blockIdx.y;
    float cy = (float)covdim(y);

    for (int i = t; i < 8192; i += 256) {
        int c = i >> 7, x = i & 127;
        float ic = 1.f / (cy * (float)covdim(x));
        size_t gi = ((size_t)(b*NC + c)*NH + y)*NW + x;
        tl[i] = g_acc_l[gi] * ic;
        th[i] = g_acc_h[gi] * ic;
    }
    for (int i = t; i < 4096; i += 256) {
        int o = i >> 6, c = i & 63;
        wl[c*WST + o] = wpl[i];
        wh[c*WST + o] = wph[i];
    }
    __syncthreads();

    int x = t & 127, og = (t >> 7) * 32;
    unsigned long long rl2[16], rh2[16];
    #pragma unroll
    for (int j = 0; j < 16; j++) { rl2[j] = 0ULL; rh2[j] = 0ULL; }

    for (int c = 0; c < 64; c++) {
        float tv = tl[c*128 + x];
        float hv = th[c*128 + x];
        unsigned long long tv2 = pk2(tv, tv);
        unsigned long long hv2 = pk2(hv, hv);
        const float* wlr = wl + c*WST + og;
        const float* whr = wh + c*WST + og;
        #pragma unroll
        for (int o4 = 0; o4 < 8; o4++) {
            float4 a4 = *(const float4*)(wlr + o4*4);
            float4 b4 = *(const float4*)(whr + o4*4);
            rl2[o4*2]   = fma2(tv2, pk2(a4.x, a4.y), rl2[o4*2]);
            rl2[o4*2+1] = fma2(tv2, pk2(a4.z, a4.w), rl2[o4*2+1]);
            rh2[o4*2]   = fma2(hv2, pk2(b4.x, b4.y), rh2[o4*2]);
            rh2[o4*2+1] = fma2(hv2, pk2(b4.z, b4.w), rh2[o4*2+1]);
        }
    }
    size_t half = (size_t)NB*NC*NPIX;
    #pragma unroll
    for (int j = 0; j < 16; j++) {
        float a, bb; upk2(a, bb, rl2[j]);
        float c2, d2; upk2(c2, d2, rh2[j]);
        int o0 = og + j*2;
        size_t gi0 = ((size_t)(b*NC + o0)*NH + y)*NW + x;
        size_t gi1 = ((size_t)(b*NC + o0 + 1)*NH + y)*NW + x;
        out[gi0]        = low[gi0]  + a;
        out[gi1]        = low[gi1]  + bb;
        out[half + gi0] = high[gi0] + c2;
        out[half + gi1] = high[gi1] + d2;
    }
}

extern "C" void kernel_launch(void* const* d_in, const int* in_sizes, int n_in,
                              void* d_out, int out_size)
{
    (void)in_sizes; (void)n_in; (void)out_size;
    const float* low  = (const float*)d_in[0];
    const float* high = (const float*)d_in[1];
    const float* w_ql = (const float*)d_in[2];
    const float* w_kh = (const float*)d_in[3];
    const float* w_vh = (const float*)d_in[4];
    const float* w_qh = (const float*)d_in[5];
    const float* w_kl = (const float*)d_in[6];
    const float* w_vl = (const float*)d_in[7];
    const float* wpl  = (const float*)d_in[8];
    const float* wph  = (const float*)d_in[9];

    void* pl; cudaGetSymbolAddress(&pl, g_acc_l);
    void* ph; cudaGetSymbolAddress(&ph, g_acc_h);
    cudaMemsetAsync(pl, 0, sizeof(float)*(size_t)NB*NC*NPIX);
    cudaMemsetAsync(ph, 0, sizeof(float)*(size_t)NB*NC*NPIX);

    cudaFuncSetAttribute(proj_kernel, cudaFuncAttributeMaxDynamicSharedMemorySize, 20480*4);
    cudaFuncSetAttribute(attn_kernel, cudaFuncAttributeMaxDynamicSharedMemorySize, 24576*4);
    cudaFuncSetAttribute(epi_kernel,  cudaFuncAttributeMaxDynamicSharedMemorySize, (16384 + 2*64*WST)*4);

    mean_kernel<<<NB*NC, 256>>>(high);
    se_kernel<<<1, 256>>>((const float*)d_in[10], (const float*)d_in[11],
                          (const float*)d_in[12], (const float*)d_in[13],
                          (const float*)d_in[14], (const float*)d_in[15]);
    proj_kernel<<<dim3(NPIX/64, NB), 256, 20480*4>>>(low, high, w_ql, w_kh, w_vh, w_qh, w_kl, w_vl);
    attn_kernel<<<dim3(NL, NB), 256, 24576*4>>>();
    epi_kernel<<<dim3(NH, NB), 256, (16384 + 2*64*WST)*4>>>(low, high, wpl, wph, (float*)d_out);
}

// round 3
// speedup vs baseline: 2.0285x; 1.0107x over previous
#include <cuda_runtime.h>

#define NB 4
#define NC 64
#define NH 128
#define NW 128
#define NPIX (NH*NW)
#define NWIN 31
#define NL (NWIN*NWIN)

// proj slot order: 0=ql 1=kh 2=vh 3=qh 4=kl 5=vl
__device__ float g_proj[6*NB*NC*NPIX];
__device__ float g_acc_l[NB*NC*NPIX];
__device__ float g_acc_h[NB*NC*NPIX];
__device__ float g_mean[NB*NC];
__device__ float g_sgate[NB*NC];

// ---------------- packed f32x2 helpers ----------------
__device__ __forceinline__ unsigned long long pk2(float lo, float hi) {
    unsigned long long r;
    asm("mov.b64 %0,{%1,%2};" : "=l"(r) : "f"(lo), "f"(hi));
    return r;
}
__device__ __forceinline__ void upk2(float& lo, float& hi, unsigned long long v) {
    asm("mov.b64 {%0,%1},%2;" : "=f"(lo), "=f"(hi) : "l"(v));
}
__device__ __forceinline__ unsigned long long fma2(unsigned long long a,
                                                   unsigned long long b,
                                                   unsigned long long c) {
    unsigned long long d;
    asm("fma.rn.f32x2 %0,%1,%2,%3;" : "=l"(d) : "l"(a), "l"(b), "l"(c));
    return d;
}
__device__ __forceinline__ unsigned long long mul2(unsigned long long a,
                                                   unsigned long long b) {
    unsigned long long d;
    asm("mul.rn.f32x2 %0,%1,%2;" : "=l"(d) : "l"(a), "l"(b));
    return d;
}

// ---------------- SE: per-channel global mean ----------------
__global__ void mean_kernel(const float* __restrict__ high) {
    int bc = blockIdx.x;
    const float* p = high + (size_t)bc * NPIX;
    float s = 0.f;
    for (int i = threadIdx.x; i < NPIX; i += 256) s += p[i];
    __shared__ float red[256];
    red[threadIdx.x] = s; __syncthreads();
    for (int k = 128; k > 0; k >>= 1) {
        if (threadIdx.x < k) red[threadIdx.x] += red[threadIdx.x + k];
        __syncthreads();
    }
    if (threadIdx.x == 0) g_mean[bc] = red[0] * (1.f/NPIX);
}

// ---------------- SE: gate per (b,c) ----------------
__global__ void se_kernel(const float* __restrict__ w10, const float* __restrict__ w20,
                          const float* __restrict__ w11, const float* __restrict__ w21,
                          const float* __restrict__ w12, const float* __restrict__ w22) {
    int t = threadIdx.x;
    int b = t >> 6, c = t & 63;
    int g  = (c < 22) ? 0 : ((c < 43) ? 1 : 2);
    int of = (g == 0) ? 0 : ((g == 1) ? 22 : 43);
    int gc = (g == 0) ? 22 : 21;
    const float* w1 = (g==0) ? w10 : ((g==1) ? w11 : w12);
    const float* w2 = (g==0) ? w20 : ((g==1) ? w21 : w22);
    float h = 0.f;
    for (int j = 0; j < gc; j++) h += g_mean[b*64 + of + j] * w1[j];
    h = fmaxf(h, 0.f);
    float v = h * w2[c - of];
    g_sgate[t] = 1.f / (1.f + __expf(-v));
}

// ---------------- global projections (fma2, o-paired transposed weights) ----------------
#define WTS 68
__global__ void __launch_bounds__(256,2) proj_kernel(
    const float* __restrict__ low, const float* __restrict__ high,
    const float* __restrict__ w_ql, const float* __restrict__ w_kh,
    const float* __restrict__ w_vh, const float* __restrict__ w_qh,
    const float* __restrict__ w_kl, const float* __restrict__ w_vl)
{
    extern __shared__ float sm[];
    float* xl = sm;            // 4096
    float* xh = sm + 4096;     // 4096
    float* wt = sm + 8192;     // 3 * 64*68 = 13056 (transposed [c][o], pad 68)

    int t = threadIdx.x;
    int pix0 = blockIdx.x * 64;
    int b = blockIdx.y;

    for (int i4 = t; i4 < 1024; i4 += 256) {
        int c = i4 >> 4, pp = (i4 & 15) * 4;
        size_t gi = (size_t)(b*NC + c)*NPIX + pix0 + pp;
        float4 vl = *(const float4*)(low + gi);
        float4 vh = *(const float4*)(high + gi);
        float gt = g_sgate[b*64 + c];
        vh.x *= gt; vh.y *= gt; vh.z *= gt; vh.w *= gt;
        *(float4*)(xl + c*64 + pp) = vl;
        *(float4*)(xh + c*64 + pp) = vh;
    }

    int ot = (t >> 4) << 2;
    int nb = (t & 15) << 2;

    for (int g = 0; g < 2; g++) {
        __syncthreads();
        const float* W0 = g ? w_kh : w_ql;
        const float* W1 = g ? w_vh : w_kl;
        const float* W2 = g ? w_qh : w_vl;
        for (int i = t; i < 12288; i += 256) {
            int p = i >> 12, j = i & 4095;
            int o = j >> 6, c = j & 63;
            const float* Wp = (p == 0) ? W0 : ((p == 1) ? W1 : W2);
            wt[p*4352 + c*WTS + o] = Wp[j];
        }
        __syncthreads();
        const float* Xs = g ? xh : xl;

        unsigned long long acc2[3][4][2];
        #pragma unroll
        for (int p = 0; p < 3; p++)
            #pragma unroll
            for (int n = 0; n < 4; n++) { acc2[p][n][0] = 0ULL; acc2[p][n][1] = 0ULL; }

        #pragma unroll 2
        for (int c0 = 0; c0 < 64; c0 += 4) {
            #pragma unroll
            for (int k = 0; k < 4; k++) {
                float4 x4 = *(const float4*)(Xs + (c0+k)*64 + nb);
                unsigned long long xd0 = pk2(x4.x, x4.x);
                unsigned long long xd1 = pk2(x4.y, x4.y);
                unsigned long long xd2 = pk2(x4.z, x4.z);
                unsigned long long xd3 = pk2(x4.w, x4.w);
                #pragma unroll
                for (int p = 0; p < 3; p++) {
                    float4 w4 = *(const float4*)(wt + p*4352 + (c0+k)*WTS + ot);
                    unsigned long long w01 = pk2(w4.x, w4.y);
                    unsigned long long w23 = pk2(w4.z, w4.w);
                    acc2[p][0][0] = fma2(xd0, w01, acc2[p][0][0]);
                    acc2[p][0][1] = fma2(xd0, w23, acc2[p][0][1]);
                    acc2[p][1][0] = fma2(xd1, w01, acc2[p][1][0]);
                    acc2[p][1][1] = fma2(xd1, w23, acc2[p][1][1]);
                    acc2[p][2][0] = fma2(xd2, w01, acc2[p][2][0]);
                    acc2[p][2][1] = fma2(xd2, w23, acc2[p][2][1]);
                    acc2[p][3][0] = fma2(xd3, w01, acc2[p][3][0]);
                    acc2[p][3][1] = fma2(xd3, w23, acc2[p][3][1]);
                }
            }
        }
        int slots[3];
        slots[0] = g ? 1 : 0; slots[1] = g ? 2 : 4; slots[2] = g ? 3 : 5;
        #pragma unroll
        for (int p = 0; p < 3; p++) {
            float lo0[4], hi0[4], lo1[4], hi1[4];
            #pragma unroll
            for (int n = 0; n < 4; n++) {
                upk2(lo0[n], hi0[n], acc2[p][n][0]);
                upk2(lo1[n], hi1[n], acc2[p][n][1]);
            }
            size_t base = (size_t)slots[p]*NB*NC*NPIX + (size_t)(b*NC)*NPIX + pix0 + nb;
            *(float4*)(g_proj + base + (size_t)(ot+0)*NPIX) = make_float4(lo0[0],lo0[1],lo0[2],lo0[3]);
            *(float4*)(g_proj + base + (size_t)(ot+1)*NPIX) = make_float4(hi0[0],hi0[1],hi0[2],hi0[3]);
            *(float4*)(g_proj + base + (size_t)(ot+2)*NPIX) = make_float4(lo1[0],lo1[1],lo1[2],lo1[3]);
            *(float4*)(g_proj + base + (size_t)(ot+3)*NPIX) = make_float4(hi1[0],hi1[1],hi1[2],hi1[3]);
        }
    }
}

// ---------------- attention (online softmax over 2 m-chunks, q from gmem) ----------------
__device__ __forceinline__ void attn_dir(
    const float* __restrict__ Qg, size_t qoff,
    const float* __restrict__ Kh, const float* __restrict__ Vh,
    float* __restrict__ gout, size_t pixoff)
{
    const float QS = 0.36067376022224085f;  // 0.25 * log2(e)
    float mx = -1e30f, ssum = 0.f;
    unsigned long long acc2[16];
    #pragma unroll
    for (int j = 0; j < 16; j++) acc2[j] = 0ULL;

    #pragma unroll
    for (int ch = 0; ch < 2; ch++) {
        unsigned long long lg2[16];
        #pragma unroll
        for (int j = 0; j < 16; j++) lg2[j] = 0ULL;
        #pragma unroll
        for (int dd = 0; dd < 16; dd++) {
            float q = Qg[(size_t)dd*NPIX + qoff] * QS;
            unsigned long long q2 = pk2(q, q);
            const float* kr = Kh + dd*64 + ch*32;
            #pragma unroll
            for (int m4 = 0; m4 < 8; m4++) {
                float4 k4 = *(const float4*)(kr + m4*4);
                lg2[m4*2]   = fma2(q2, pk2(k4.x, k4.y), lg2[m4*2]);
                lg2[m4*2+1] = fma2(q2, pk2(k4.z, k4.w), lg2[m4*2+1]);
            }
        }
        float cm = -1e30f;
        #pragma unroll
        for (int j = 0; j < 16; j++) {
            float a, bb; upk2(a, bb, lg2[j]);
            cm = fmaxf(cm, fmaxf(a, bb));
        }
        float nmx = fmaxf(mx, cm);
        float rs = exp2f(mx - nmx);
        mx = nmx; ssum *= rs;
        unsigned long long rs2 = pk2(rs, rs);
        #pragma unroll
        for (int j = 0; j < 16; j++) acc2[j] = mul2(acc2[j], rs2);
        #pragma unroll
        for (int j = 0; j < 16; j++) {
            float a, bb; upk2(a, bb, lg2[j]);
            a = exp2f(a - mx); bb = exp2f(bb - mx);
            ssum += a + bb;
            lg2[j] = pk2(a, bb);
        }
        #pragma unroll
        for (int dd = 0; dd < 16; dd++) {
            const float* vr = Vh + dd*64 + ch*32;
            unsigned long long a2 = acc2[dd];
            #pragma unroll
            for (int m4 = 0; m4 < 8; m4++) {
                float4 v4 = *(const float4*)(vr + m4*4);
                a2 = fma2(lg2[m4*2],   pk2(v4.x, v4.y), a2);
                a2 = fma2(lg2[m4*2+1], pk2(v4.z, v4.w), a2);
            }
            acc2[dd] = a2;
        }
    }
    float inv = 1.f / ssum;
    #pragma unroll
    for (int dd = 0; dd < 16; dd++) {
        float a, bb; upk2(a, bb, acc2[dd]);
        atomicAdd(gout + (size_t)dd*NPIX + pixoff, (a + bb) * inv);
    }
}

__global__ void __launch_bounds__(256, 3) attn_kernel()
{
    extern __shared__ float Y[];  // 4 tiles: kh, vh, kl, vl

    int t = threadIdx.x;
    int l = blockIdx.x, b = blockIdx.y;
    int y0 = (l / NWIN) * 4, x0 = (l % NWIN) * 4;

    // load 4 K/V tiles (slots 1,2,4,5)
    for (int i4 = t; i4 < 4096; i4 += 256) {
        int p = i4 >> 10, rem = i4 & 1023;
        int slot = (p < 2) ? (p + 1) : (p + 2);
        int c = rem >> 4, q4 = rem & 15;
        int r = q4 >> 1, cc = (q4 & 1) * 4;
        size_t gi = ((size_t)slot*NB*NC + (size_t)(b*NC + c))*NPIX + (size_t)(y0 + r)*NW + x0 + cc;
        *(float4*)(Y + p*4096 + c*64 + r*8 + cc) = *(const float4*)(g_proj + gi);
    }
    __syncthreads();

    int h = t >> 6, n = t & 63;
    int r = n >> 3, cc = n & 7;
    size_t pixoff = (size_t)(y0 + r)*NW + x0 + cc;

    const float* qlg = g_proj + ((size_t)(b*NC + h*16))*NPIX;                           // slot0
    const float* qhg = g_proj + ((size_t)3*NB*NC + (size_t)(b*NC + h*16))*NPIX;         // slot3

    attn_dir(qlg, pixoff, Y + 0*4096 + h*1024, Y + 1*4096 + h*1024,
             g_acc_l + ((size_t)(b*NC + h*16))*NPIX, pixoff);
    attn_dir(qhg, pixoff, Y + 2*4096 + h*1024, Y + 3*4096 + h*1024,
             g_acc_h + ((size_t)(b*NC + h*16))*NPIX, pixoff);
}

// ---------------- epilogue: normalize fold, 1x1 proj + residual ----------------
__device__ __forceinline__ int covdim(int y) {
    int imin = (y >= 8) ? ((y - 4) >> 2) : 0;
    int imax = y >> 2; if (imax > 30) imax = 30;
    return imax - imin + 1;
}

#define WST 72

__global__ void __launch_bounds__(256) epi_kernel(
    const float* __restrict__ low, const float* __restrict__ high,
    const float* __restrict__ wpl, const float* __restrict__ wph,
    float* __restrict__ out)
{
    extern __shared__ float sm[];
    float* tl = sm;                    // 8192
    float* th = sm + 8192;             // 8192
    float* wl = sm + 16384;            // 64*WST
    float* wh = sm + 16384 + 64*WST;   // 64*WST

    int t = threadIdx.x;
    int y = blockIdx.x, b = blockIdx.y;
    float cy = (float)covdim(y);

    for (int i = t; i < 8192; i += 256) {
        int c = i >> 7, x = i & 127;
        float ic = 1.f / (cy * (float)covdim(x));
        size_t gi = ((size_t)(b*NC + c)*NH + y)*NW + x;
        tl[i] = g_acc_l[gi] * ic;
        th[i] = g_acc_h[gi] * ic;
    }
    for (int i = t; i < 4096; i += 256) {
        int o = i >> 6, c = i & 63;
        wl[c*WST + o] = wpl[i];
        wh[c*WST + o] = wph[i];
    }
    __syncthreads();

    int x = t & 127, og = (t >> 7) * 32;
    unsigned long long rl2[16], rh2[16];
    #pragma unroll
    for (int j = 0; j < 16; j++) { rl2[j] = 0ULL; rh2[j] = 0ULL; }

    for (int c = 0; c < 64; c++) {
        float tv = tl[c*128 + x];
        float hv = th[c*128 + x];
        unsigned long long tv2 = pk2(tv, tv);
        unsigned long long hv2 = pk2(hv, hv);
        const float* wlr = wl + c*WST + og;
        const float* whr = wh + c*WST + og;
        #pragma unroll
        for (int o4 = 0; o4 < 8; o4++) {
            float4 a4 = *(const float4*)(wlr + o4*4);
            float4 b4 = *(const float4*)(whr + o4*4);
            rl2[o4*2]   = fma2(tv2, pk2(a4.x, a4.y), rl2[o4*2]);
            rl2[o4*2+1] = fma2(tv2, pk2(a4.z, a4.w), rl2[o4*2+1]);
            rh2[o4*2]   = fma2(hv2, pk2(b4.x, b4.y), rh2[o4*2]);
            rh2[o4*2+1] = fma2(hv2, pk2(b4.z, b4.w), rh2[o4*2+1]);
        }
    }
    size_t half = (size_t)NB*NC*NPIX;
    #pragma unroll
    for (int j = 0; j < 16; j++) {
        float a, bb; upk2(a, bb, rl2[j]);
        float c2, d2; upk2(c2, d2, rh2[j]);
        int o0 = og + j*2;
        size_t gi0 = ((size_t)(b*NC + o0)*NH + y)*NW + x;
        size_t gi1 = ((size_t)(b*NC + o0 + 1)*NH + y)*NW + x;
        out[gi0]        = low[gi0]  + a;
        out[gi1]        = low[gi1]  + bb;
        out[half + gi0] = high[gi0] + c2;
        out[half + gi1] = high[gi1] + d2;
    }
}

extern "C" void kernel_launch(void* const* d_in, const int* in_sizes, int n_in,
                              void* d_out, int out_size)
{
    (void)in_sizes; (void)n_in; (void)out_size;
    const float* low  = (const float*)d_in[0];
    const float* high = (const float*)d_in[1];
    const float* w_ql = (const float*)d_in[2];
    const float* w_kh = (const float*)d_in[3];
    const float* w_vh = (const float*)d_in[4];
    const float* w_qh = (const float*)d_in[5];
    const float* w_kl = (const float*)d_in[6];
    const float* w_vl = (const float*)d_in[7];
    const float* wpl  = (const float*)d_in[8];
    const float* wph  = (const float*)d_in[9];

    void* pl; cudaGetSymbolAddress(&pl, g_acc_l);
    void* ph; cudaGetSymbolAddress(&ph, g_acc_h);
    cudaMemsetAsync(pl, 0, sizeof(float)*(size_t)NB*NC*NPIX);
    cudaMemsetAsync(ph, 0, sizeof(float)*(size_t)NB*NC*NPIX);

    cudaFuncSetAttribute(proj_kernel, cudaFuncAttributeMaxDynamicSharedMemorySize, (8192+13056)*4);
    cudaFuncSetAttribute(attn_kernel, cudaFuncAttributeMaxDynamicSharedMemorySize, 16384*4);
    cudaFuncSetAttribute(epi_kernel,  cudaFuncAttributeMaxDynamicSharedMemorySize, (16384 + 2*64*WST)*4);

    mean_kernel<<<NB*NC, 256>>>(high);
    se_kernel<<<1, 256>>>((const float*)d_in[10], (const float*)d_in[11],
                          (const float*)d_in[12], (const float*)d_in[13],
                          (const float*)d_in[14], (const float*)d_in[15]);
    proj_kernel<<<dim3(NPIX/64, NB), 256, (8192+13056)*4>>>(low, high, w_ql, w_kh, w_vh, w_qh, w_kl, w_vl);
    attn_kernel<<<dim3(NL, NB), 256, 16384*4>>>();
    epi_kernel<<<dim3(NH, NB), 256, (16384 + 2*64*WST)*4>>>(low, high, wpl, wph, (float*)d_out);
}

// round 4
// speedup vs baseline: 2.0413x; 1.0063x over previous
#include <cuda_runtime.h>

#define NB 4
#define NC 64
#define NH 128
#define NW 128
#define NPIX (NH*NW)
#define NWIN 31
#define NL (NWIN*NWIN)

typedef unsigned long long u64;

// proj slot order: 0=ql 1=kh 2=vh 3=qh 4=kl 5=vl
__device__ float g_proj[6*NB*NC*NPIX];
__device__ float g_acc_l[NB*NC*NPIX];
__device__ float g_acc_h[NB*NC*NPIX];
__device__ float g_mean[NB*NC];
__device__ float g_sgate[NB*NC];

// ---------------- packed f32x2 helpers ----------------
__device__ __forceinline__ u64 pk2(float lo, float hi) {
    u64 r;
    asm("mov.b64 %0,{%1,%2};" : "=l"(r) : "f"(lo), "f"(hi));
    return r;
}
__device__ __forceinline__ void upk2(float& lo, float& hi, u64 v) {
    asm("mov.b64 {%0,%1},%2;" : "=f"(lo), "=f"(hi) : "l"(v));
}
__device__ __forceinline__ u64 fma2(u64 a, u64 b, u64 c) {
    u64 d;
    asm("fma.rn.f32x2 %0,%1,%2,%3;" : "=l"(d) : "l"(a), "l"(b), "l"(c));
    return d;
}

// ---------------- SE: per-channel global mean ----------------
__global__ void mean_kernel(const float* __restrict__ high) {
    int bc = blockIdx.x;
    const float* p = high + (size_t)bc * NPIX;
    float s = 0.f;
    for (int i = threadIdx.x; i < NPIX; i += 256) s += p[i];
    __shared__ float red[256];
    red[threadIdx.x] = s; __syncthreads();
    for (int k = 128; k > 0; k >>= 1) {
        if (threadIdx.x < k) red[threadIdx.x] += red[threadIdx.x + k];
        __syncthreads();
    }
    if (threadIdx.x == 0) g_mean[bc] = red[0] * (1.f/NPIX);
}

// ---------------- SE: gate per (b,c) ----------------
__global__ void se_kernel(const float* __restrict__ w10, const float* __restrict__ w20,
                          const float* __restrict__ w11, const float* __restrict__ w21,
                          const float* __restrict__ w12, const float* __restrict__ w22) {
    int t = threadIdx.x;
    int b = t >> 6, c = t & 63;
    int g  = (c < 22) ? 0 : ((c < 43) ? 1 : 2);
    int of = (g == 0) ? 0 : ((g == 1) ? 22 : 43);
    int gc = (g == 0) ? 22 : 21;
    const float* w1 = (g==0) ? w10 : ((g==1) ? w11 : w12);
    const float* w2 = (g==0) ? w20 : ((g==1) ? w21 : w22);
    float h = 0.f;
    for (int j = 0; j < gc; j++) h += g_mean[b*64 + of + j] * w1[j];
    h = fmaxf(h, 0.f);
    float v = h * w2[c - of];
    g_sgate[t] = 1.f / (1.f + __expf(-v));
}

// ---------------- global projections (fma2, direct u64 weight loads) ----------------
#define WTS 68
__global__ void __launch_bounds__(256,2) proj_kernel(
    const float* __restrict__ low, const float* __restrict__ high,
    const float* __restrict__ w_ql, const float* __restrict__ w_kh,
    const float* __restrict__ w_vh, const float* __restrict__ w_qh,
    const float* __restrict__ w_kl, const float* __restrict__ w_vl)
{
    extern __shared__ float sm[];
    float* xl = sm;            // 4096
    float* xh = sm + 4096;     // 4096
    float* wt = sm + 8192;     // 3 * 64*68

    int t = threadIdx.x;
    int pix0 = blockIdx.x * 64;
    int b = blockIdx.y;

    for (int i4 = t; i4 < 1024; i4 += 256) {
        int c = i4 >> 4, pp = (i4 & 15) * 4;
        size_t gi = (size_t)(b*NC + c)*NPIX + pix0 + pp;
        float4 vl = *(const float4*)(low + gi);
        float4 vh = *(const float4*)(high + gi);
        float gt = g_sgate[b*64 + c];
        vh.x *= gt; vh.y *= gt; vh.z *= gt; vh.w *= gt;
        *(float4*)(xl + c*64 + pp) = vl;
        *(float4*)(xh + c*64 + pp) = vh;
    }

    int ot = (t >> 4) << 2;
    int nb = (t & 15) << 2;

    for (int g = 0; g < 2; g++) {
        __syncthreads();
        const float* W0 = g ? w_kh : w_ql;
        const float* W1 = g ? w_vh : w_kl;
        const float* W2 = g ? w_qh : w_vl;
        for (int i = t; i < 12288; i += 256) {
            int p = i >> 12, j = i & 4095;
            int o = j >> 6, c = j & 63;
            const float* Wp = (p == 0) ? W0 : ((p == 1) ? W1 : W2);
            wt[p*4352 + c*WTS + o] = Wp[j];
        }
        __syncthreads();
        const float* Xs = g ? xh : xl;

        u64 acc2[3][4][2];
        #pragma unroll
        for (int p = 0; p < 3; p++)
            #pragma unroll
            for (int n = 0; n < 4; n++) { acc2[p][n][0] = 0ULL; acc2[p][n][1] = 0ULL; }

        #pragma unroll 2
        for (int c0 = 0; c0 < 64; c0 += 4) {
            #pragma unroll
            for (int k = 0; k < 4; k++) {
                float4 x4 = *(const float4*)(Xs + (c0+k)*64 + nb);
                u64 xd0 = pk2(x4.x, x4.x);
                u64 xd1 = pk2(x4.y, x4.y);
                u64 xd2 = pk2(x4.z, x4.z);
                u64 xd3 = pk2(x4.w, x4.w);
                #pragma unroll
                for (int p = 0; p < 3; p++) {
                    ulonglong2 w2v = *(const ulonglong2*)(wt + p*4352 + (c0+k)*WTS + ot);
                    acc2[p][0][0] = fma2(xd0, w2v.x, acc2[p][0][0]);
                    acc2[p][0][1] = fma2(xd0, w2v.y, acc2[p][0][1]);
                    acc2[p][1][0] = fma2(xd1, w2v.x, acc2[p][1][0]);
                    acc2[p][1][1] = fma2(xd1, w2v.y, acc2[p][1][1]);
                    acc2[p][2][0] = fma2(xd2, w2v.x, acc2[p][2][0]);
                    acc2[p][2][1] = fma2(xd2, w2v.y, acc2[p][2][1]);
                    acc2[p][3][0] = fma2(xd3, w2v.x, acc2[p][3][0]);
                    acc2[p][3][1] = fma2(xd3, w2v.y, acc2[p][3][1]);
                }
            }
        }
        int slots[3];
        slots[0] = g ? 1 : 0; slots[1] = g ? 2 : 4; slots[2] = g ? 3 : 5;
        #pragma unroll
        for (int p = 0; p < 3; p++) {
            float lo0[4], hi0[4], lo1[4], hi1[4];
            #pragma unroll
            for (int n = 0; n < 4; n++) {
                upk2(lo0[n], hi0[n], acc2[p][n][0]);
                upk2(lo1[n], hi1[n], acc2[p][n][1]);
            }
            size_t base = (size_t)slots[p]*NB*NC*NPIX + (size_t)(b*NC)*NPIX + pix0 + nb;
            *(float4*)(g_proj + base + (size_t)(ot+0)*NPIX) = make_float4(lo0[0],lo0[1],lo0[2],lo0[3]);
            *(float4*)(g_proj + base + (size_t)(ot+1)*NPIX) = make_float4(hi0[0],hi0[1],hi0[2],hi0[3]);
            *(float4*)(g_proj + base + (size_t)(ot+2)*NPIX) = make_float4(lo1[0],lo1[1],lo1[2],lo1[3]);
            *(float4*)(g_proj + base + (size_t)(ot+3)*NPIX) = make_float4(hi1[0],hi1[1],hi1[2],hi1[3]);
        }
    }
}

// ---------------- attention: R=2 n-blocking, direct u64 K/V loads, no-max softmax ----------------
__device__ __forceinline__ void attn_dir(
    const float* __restrict__ Yq, const float* __restrict__ Yk, const float* __restrict__ Yv,
    float* __restrict__ gout, int nA, int nB, size_t pixA, size_t pixB)
{
    const float QS = 0.36067376022224085f;  // 0.25 * log2(e)

    float qa[16], qb[16];
    #pragma unroll
    for (int dd = 0; dd < 16; dd++) {
        qa[dd] = Yq[dd*64 + nA] * QS;
        qb[dd] = Yq[dd*64 + nB] * QS;
    }

    u64 accA[16], accB[16];
    #pragma unroll
    for (int j = 0; j < 16; j++) { accA[j] = 0ULL; accB[j] = 0ULL; }
    float sumA = 0.f, sumB = 0.f;

    #pragma unroll
    for (int ch = 0; ch < 4; ch++) {
        u64 lgA[8], lgB[8];
        #pragma unroll
        for (int j = 0; j < 8; j++) { lgA[j] = 0ULL; lgB[j] = 0ULL; }

        #pragma unroll
        for (int dd = 0; dd < 16; dd++) {
            u64 qa2 = pk2(qa[dd], qa[dd]);
            u64 qb2 = pk2(qb[dd], qb[dd]);
            const ulonglong2* kr = (const ulonglong2*)(Yk + dd*64 + ch*16);
            #pragma unroll
            for (int j2 = 0; j2 < 4; j2++) {
                ulonglong2 kk = kr[j2];
                lgA[j2*2]   = fma2(qa2, kk.x, lgA[j2*2]);
                lgA[j2*2+1] = fma2(qa2, kk.y, lgA[j2*2+1]);
                lgB[j2*2]   = fma2(qb2, kk.x, lgB[j2*2]);
                lgB[j2*2+1] = fma2(qb2, kk.y, lgB[j2*2+1]);
            }
        }
        // exp (no max subtraction: |logit| small, fp32 safe; softmax shift-invariant)
        #pragma unroll
        for (int j = 0; j < 8; j++) {
            float a, bb; upk2(a, bb, lgA[j]);
            a = exp2f(a); bb = exp2f(bb);
            sumA += a + bb;
            lgA[j] = pk2(a, bb);
            float c, d; upk2(c, d, lgB[j]);
            c = exp2f(c); d = exp2f(d);
            sumB += c + d;
            lgB[j] = pk2(c, d);
        }
        // AV accumulate
        #pragma unroll
        for (int dd = 0; dd < 16; dd++) {
            const ulonglong2* vr = (const ulonglong2*)(Yv + dd*64 + ch*16);
            u64 aA = accA[dd], aB = accB[dd];
            #pragma unroll
            for (int j2 = 0; j2 < 4; j2++) {
                ulonglong2 vv = vr[j2];
                aA = fma2(lgA[j2*2],   vv.x, aA);
                aA = fma2(lgA[j2*2+1], vv.y, aA);
                aB = fma2(lgB[j2*2],   vv.x, aB);
                aB = fma2(lgB[j2*2+1], vv.y, aB);
            }
            accA[dd] = aA; accB[dd] = aB;
        }
    }
    float invA = 1.f / sumA, invB = 1.f / sumB;
    #pragma unroll
    for (int dd = 0; dd < 16; dd++) {
        float a, bb; upk2(a, bb, accA[dd]);
        float c, d; upk2(c, d, accB[dd]);
        atomicAdd(gout + (size_t)dd*NPIX + pixA, (a + bb) * invA);
        atomicAdd(gout + (size_t)dd*NPIX + pixB, (c + d) * invB);
    }
}

__global__ void __launch_bounds__(128, 3) attn_kernel()
{
    extern __shared__ float Y[];  // 6 tiles: ql kh vh qh kl vl (4KB each)

    int t = threadIdx.x;
    int l = blockIdx.x, b = blockIdx.y;
    int y0 = (l / NWIN) * 4, x0 = (l % NWIN) * 4;

    // stage all 6 projected tiles (float4, coalesced 32B rows)
    for (int i4 = t; i4 < 6144; i4 += 128) {
        int p = i4 >> 10, rem = i4 & 1023;
        int c = rem >> 4, q4 = rem & 15;
        int r = q4 >> 1, cc = (q4 & 1) * 4;
        size_t gi = ((size_t)p*NB*NC + (size_t)(b*NC + c))*NPIX + (size_t)(y0 + r)*NW + x0 + cc;
        *(float4*)(Y + p*4096 + c*64 + r*8 + cc) = *(const float4*)(g_proj + gi);
    }
    __syncthreads();

    int h = t >> 5, lane = t & 31;
    int nA = lane, nB = lane + 32;
    size_t pixA = (size_t)(y0 + (nA >> 3))*NW + x0 + (nA & 7);
    size_t pixB = (size_t)(y0 + (nB >> 3))*NW + x0 + (nB & 7);

    int hb = h * 1024;
    float* outl = g_acc_l + ((size_t)(b*NC + h*16))*NPIX;
    float* outh = g_acc_h + ((size_t)(b*NC + h*16))*NPIX;

    // dir1: ql . kh -> vh into acc_l
    attn_dir(Y + 0*4096 + hb, Y + 1*4096 + hb, Y + 2*4096 + hb, outl, nA, nB, pixA, pixB);
    // dir2: qh . kl -> vl into acc_h
    attn_dir(Y + 3*4096 + hb, Y + 4*4096 + hb, Y + 5*4096 + hb, outh, nA, nB, pixA, pixB);
}

// ---------------- epilogue: normalize fold, 1x1 proj + residual ----------------
__device__ __forceinline__ int covdim(int y) {
    int imin = (y >= 8) ? ((y - 4) >> 2) : 0;
    int imax = y >> 2; if (imax > 30) imax = 30;
    return imax - imin + 1;
}

#define WST 72

__global__ void __launch_bounds__(256) epi_kernel(
    const float* __restrict__ low, const float* __restrict__ high,
    const float* __restrict__ wpl, const float* __restrict__ wph,
    float* __restrict__ out)
{
    extern __shared__ float sm[];
    float* tl = sm;                    // 8192
    float* th = sm + 8192;             // 8192
    float* wl = sm + 16384;            // 64*WST
    float* wh = sm + 16384 + 64*WST;   // 64*WST

    int t = threadIdx.x;
    int y = blockIdx.x, b = blockIdx.y;
    float cy = (float)covdim(y);

    for (int i = t; i < 8192; i += 256) {
        int c = i >> 7, x = i & 127;
        float ic = 1.f / (cy * (float)covdim(x));
        size_t gi = ((size_t)(b*NC + c)*NH + y)*NW + x;
        tl[i] = g_acc_l[gi] * ic;
        th[i] = g_acc_h[gi] * ic;
    }
    for (int i = t; i < 4096; i += 256) {
        int o = i >> 6, c = i & 63;
        wl[c*WST + o] = wpl[i];
        wh[c*WST + o] = wph[i];
    }
    __syncthreads();

    int x = t & 127, og = (t >> 7) * 32;
    u64 rl2[16], rh2[16];
    #pragma unroll
    for (int j = 0; j < 16; j++) { rl2[j] = 0ULL; rh2[j] = 0ULL; }

    for (int c = 0; c < 64; c++) {
        float tv = tl[c*128 + x];
        float hv = th[c*128 + x];
        u64 tv2 = pk2(tv, tv);
        u64 hv2 = pk2(hv, hv);
        const ulonglong2* wlr = (const ulonglong2*)(wl + c*WST + og);
        const ulonglong2* whr = (const ulonglong2*)(wh + c*WST + og);
        #pragma unroll
        for (int o4 = 0; o4 < 8; o4++) {
            ulonglong2 a2 = wlr[o4];
            ulonglong2 b2 = whr[o4];
            rl2[o4*2]   = fma2(tv2, a2.x, rl2[o4*2]);
            rl2[o4*2+1] = fma2(tv2, a2.y, rl2[o4*2+1]);
            rh2[o4*2]   = fma2(hv2, b2.x, rh2[o4*2]);
            rh2[o4*2+1] = fma2(hv2, b2.y, rh2[o4*2+1]);
        }
    }
    size_t half = (size_t)NB*NC*NPIX;
    #pragma unroll
    for (int j = 0; j < 16; j++) {
        float a, bb; upk2(a, bb, rl2[j]);
        float c2, d2; upk2(c2, d2, rh2[j]);
        int o0 = og + j*2;
        size_t gi0 = ((size_t)(b*NC + o0)*NH + y)*NW + x;
        size_t gi1 = ((size_t)(b*NC + o0 + 1)*NH + y)*NW + x;
        out[gi0]        = low[gi0]  + a;
        out[gi1]        = low[gi1]  + bb;
        out[half + gi0] = high[gi0] + c2;
        out[half + gi1] = high[gi1] + d2;
    }
}

extern "C" void kernel_launch(void* const* d_in, const int* in_sizes, int n_in,
                              void* d_out, int out_size)
{
    (void)in_sizes; (void)n_in; (void)out_size;
    const float* low  = (const float*)d_in[0];
    const float* high = (const float*)d_in[1];
    const float* w_ql = (const float*)d_in[2];
    const float* w_kh = (const float*)d_in[3];
    const float* w_vh = (const float*)d_in[4];
    const float* w_qh = (const float*)d_in[5];
    const float* w_kl = (const float*)d_in[6];
    const float* w_vl = (const float*)d_in[7];
    const float* wpl  = (const float*)d_in[8];
    const float* wph  = (const float*)d_in[9];

    void* pl; cudaGetSymbolAddress(&pl, g_acc_l);
    void* ph; cudaGetSymbolAddress(&ph, g_acc_h);
    cudaMemsetAsync(pl, 0, sizeof(float)*(size_t)NB*NC*NPIX);
    cudaMemsetAsync(ph, 0, sizeof(float)*(size_t)NB*NC*NPIX);

    cudaFuncSetAttribute(proj_kernel, cudaFuncAttributeMaxDynamicSharedMemorySize, (8192+13056)*4);
    cudaFuncSetAttribute(attn_kernel, cudaFuncAttributeMaxDynamicSharedMemorySize, 24576*4);
    cudaFuncSetAttribute(epi_kernel,  cudaFuncAttributeMaxDynamicSharedMemorySize, (16384 + 2*64*WST)*4);

    mean_kernel<<<NB*NC, 256>>>(high);
    se_kernel<<<1, 256>>>((const float*)d_in[10], (const float*)d_in[11],
                          (const float*)d_in[12], (const float*)d_in[13],
                          (const float*)d_in[14], (const float*)d_in[15]);
    proj_kernel<<<dim3(NPIX/64, NB), 256, (8192+13056)*4>>>(low, high, w_ql, w_kh, w_vh, w_qh, w_kl, w_vl);
    attn_kernel<<<dim3(NL, NB), 128, 24576*4>>>();
    epi_kernel<<<dim3(NH, NB), 256, (16384 + 2*64*WST)*4>>>(low, high, wpl, wph, (float*)d_out);
}

// round 5
// speedup vs baseline: 2.2837x; 1.1187x over previous
#include <cuda_runtime.h>

#define NB 4
#define NC 64
#define NH 128
#define NW 128
#define NPIX (NH*NW)
#define NWIN 31
#define NL (NWIN*NWIN)

typedef unsigned long long u64;

// proj slot order: 0=ql 1=kh 2=vh 3=qh 4=kl 5=vl  (dir0 uses 0,1,2; dir1 uses 3,4,5)
__device__ float g_proj[6*NB*NC*NPIX];
__device__ float g_acc_l[NB*NC*NPIX];
__device__ float g_acc_h[NB*NC*NPIX];
__device__ float g_mean[NB*NC];
__device__ float g_sgate[NB*NC];

// ---------------- packed f32x2 helpers ----------------
__device__ __forceinline__ u64 pk2(float lo, float hi) {
    u64 r;
    asm("mov.b64 %0,{%1,%2};" : "=l"(r) : "f"(lo), "f"(hi));
    return r;
}
__device__ __forceinline__ void upk2(float& lo, float& hi, u64 v) {
    asm("mov.b64 {%0,%1},%2;" : "=f"(lo), "=f"(hi) : "l"(v));
}
__device__ __forceinline__ u64 fma2(u64 a, u64 b, u64 c) {
    u64 d;
    asm("fma.rn.f32x2 %0,%1,%2,%3;" : "=l"(d) : "l"(a), "l"(b), "l"(c));
    return d;
}
__device__ __forceinline__ u64 add2(u64 a, u64 b) {
    u64 d;
    asm("add.rn.f32x2 %0,%1,%2;" : "=l"(d) : "l"(a), "l"(b));
    return d;
}

// ---------------- SE: per-channel global mean ----------------
__global__ void mean_kernel(const float* __restrict__ high) {
    int bc = blockIdx.x;
    const float* p = high + (size_t)bc * NPIX;
    float s = 0.f;
    for (int i = threadIdx.x; i < NPIX; i += 256) s += p[i];
    __shared__ float red[256];
    red[threadIdx.x] = s; __syncthreads();
    for (int k = 128; k > 0; k >>= 1) {
        if (threadIdx.x < k) red[threadIdx.x] += red[threadIdx.x + k];
        __syncthreads();
    }
    if (threadIdx.x == 0) g_mean[bc] = red[0] * (1.f/NPIX);
}

// ---------------- SE: gate per (b,c) ----------------
__global__ void se_kernel(const float* __restrict__ w10, const float* __restrict__ w20,
                          const float* __restrict__ w11, const float* __restrict__ w21,
                          const float* __restrict__ w12, const float* __restrict__ w22) {
    int t = threadIdx.x;
    int b = t >> 6, c = t & 63;
    int g  = (c < 22) ? 0 : ((c < 43) ? 1 : 2);
    int of = (g == 0) ? 0 : ((g == 1) ? 22 : 43);
    int gc = (g == 0) ? 22 : 21;
    const float* w1 = (g==0) ? w10 : ((g==1) ? w11 : w12);
    const float* w2 = (g==0) ? w20 : ((g==1) ? w21 : w22);
    float h = 0.f;
    for (int j = 0; j < gc; j++) h += g_mean[b*64 + of + j] * w1[j];
    h = fmaxf(h, 0.f);
    float v = h * w2[c - of];
    g_sgate[t] = 1.f / (1.f + __expf(-v));
}

// ---------------- global projections (fma2; q-weights pre-scaled by 0.25*log2e) ----------------
#define WTS 68
#define QS 0.36067376022224085f
__global__ void __launch_bounds__(256,2) proj_kernel(
    const float* __restrict__ low, const float* __restrict__ high,
    const float* __restrict__ w_ql, const float* __restrict__ w_kh,
    const float* __restrict__ w_vh, const float* __restrict__ w_qh,
    const float* __restrict__ w_kl, const float* __restrict__ w_vl)
{
    extern __shared__ float sm[];
    float* xl = sm;            // 4096
    float* xh = sm + 4096;     // 4096
    float* wt = sm + 8192;     // 3 * 64*68

    int t = threadIdx.x;
    int pix0 = blockIdx.x * 64;
    int b = blockIdx.y;

    for (int i4 = t; i4 < 1024; i4 += 256) {
        int c = i4 >> 4, pp = (i4 & 15) * 4;
        size_t gi = (size_t)(b*NC + c)*NPIX + pix0 + pp;
        float4 vl = *(const float4*)(low + gi);
        float4 vh = *(const float4*)(high + gi);
        float gt = g_sgate[b*64 + c];
        vh.x *= gt; vh.y *= gt; vh.z *= gt; vh.w *= gt;
        *(float4*)(xl + c*64 + pp) = vl;
        *(float4*)(xh + c*64 + pp) = vh;
    }

    int ot = (t >> 4) << 2;
    int nb = (t & 15) << 2;

    for (int g = 0; g < 2; g++) {
        __syncthreads();
        const float* W0 = g ? w_kh : w_ql;
        const float* W1 = g ? w_vh : w_kl;
        const float* W2 = g ? w_qh : w_vl;
        for (int i = t; i < 12288; i += 256) {
            int p = i >> 12, j = i & 4095;
            int o = j >> 6, c = j & 63;
            const float* Wp = (p == 0) ? W0 : ((p == 1) ? W1 : W2);
            float wv = Wp[j];
            // fold attention scale into q-projection weights (slot0 / slot3)
            if ((g == 0 && p == 0) || (g == 1 && p == 2)) wv *= QS;
            wt[p*4352 + c*WTS + o] = wv;
        }
        __syncthreads();
        const float* Xs = g ? xh : xl;

        u64 acc2[3][4][2];
        #pragma unroll
        for (int p = 0; p < 3; p++)
            #pragma unroll
            for (int n = 0; n < 4; n++) { acc2[p][n][0] = 0ULL; acc2[p][n][1] = 0ULL; }

        #pragma unroll 2
        for (int c0 = 0; c0 < 64; c0 += 4) {
            #pragma unroll
            for (int k = 0; k < 4; k++) {
                float4 x4 = *(const float4*)(Xs + (c0+k)*64 + nb);
                u64 xd0 = pk2(x4.x, x4.x);
                u64 xd1 = pk2(x4.y, x4.y);
                u64 xd2 = pk2(x4.z, x4.z);
                u64 xd3 = pk2(x4.w, x4.w);
                #pragma unroll
                for (int p = 0; p < 3; p++) {
                    ulonglong2 w2v = *(const ulonglong2*)(wt + p*4352 + (c0+k)*WTS + ot);
                    acc2[p][0][0] = fma2(xd0, w2v.x, acc2[p][0][0]);
                    acc2[p][0][1] = fma2(xd0, w2v.y, acc2[p][0][1]);
                    acc2[p][1][0] = fma2(xd1, w2v.x, acc2[p][1][0]);
                    acc2[p][1][1] = fma2(xd1, w2v.y, acc2[p][1][1]);
                    acc2[p][2][0] = fma2(xd2, w2v.x, acc2[p][2][0]);
                    acc2[p][2][1] = fma2(xd2, w2v.y, acc2[p][2][1]);
                    acc2[p][3][0] = fma2(xd3, w2v.x, acc2[p][3][0]);
                    acc2[p][3][1] = fma2(xd3, w2v.y, acc2[p][3][1]);
                }
            }
        }
        int slots[3];
        slots[0] = g ? 1 : 0; slots[1] = g ? 2 : 4; slots[2] = g ? 3 : 5;
        #pragma unroll
        for (int p = 0; p < 3; p++) {
            float lo0[4], hi0[4], lo1[4], hi1[4];
            #pragma unroll
            for (int n = 0; n < 4; n++) {
                upk2(lo0[n], hi0[n], acc2[p][n][0]);
                upk2(lo1[n], hi1[n], acc2[p][n][1]);
            }
            size_t base = (size_t)slots[p]*NB*NC*NPIX + (size_t)(b*NC)*NPIX + pix0 + nb;
            *(float4*)(g_proj + base + (size_t)(ot+0)*NPIX) = make_float4(lo0[0],lo0[1],lo0[2],lo0[3]);
            *(float4*)(g_proj + base + (size_t)(ot+1)*NPIX) = make_float4(hi0[0],hi0[1],hi0[2],hi0[3]);
            *(float4*)(g_proj + base + (size_t)(ot+2)*NPIX) = make_float4(lo1[0],lo1[1],lo1[2],lo1[3]);
            *(float4*)(g_proj + base + (size_t)(ot+3)*NPIX) = make_float4(hi1[0],hi1[1],hi1[2],hi1[3]);
        }
    }
}

// ---------------- attention: one (window, dir, batch) per block; 48KB smem ----------------
__global__ void __launch_bounds__(128, 4) attn_kernel()
{
    extern __shared__ float Y[];  // q[4096] k[4096] v[4096]

    int t = threadIdx.x;
    int l = blockIdx.x, dir = blockIdx.y, b = blockIdx.z;
    int y0 = (l / NWIN) * 4, x0 = (l % NWIN) * 4;

    // stage this direction's 3 tiles (slots dir*3 + {0,1,2})
    for (int i4 = t; i4 < 3072; i4 += 128) {
        int p = i4 >> 10, rem = i4 & 1023;
        int slot = dir*3 + p;
        int c = rem >> 4, q4 = rem & 15;
        int r = q4 >> 1, cc = (q4 & 1) * 4;
        size_t gi = ((size_t)slot*NB*NC + (size_t)(b*NC + c))*NPIX + (size_t)(y0 + r)*NW + x0 + cc;
        *(float4*)(Y + p*4096 + c*64 + r*8 + cc) = *(const float4*)(g_proj + gi);
    }
    __syncthreads();

    int h = t >> 5, lane = t & 31;
    int nA = lane, nB = lane + 32;
    size_t pixA = (size_t)(y0 + (nA >> 3))*NW + x0 + (nA & 7);
    size_t pixB = (size_t)(y0 + (nB >> 3))*NW + x0 + (nB & 7);

    const float* Yq = Y + h*1024;
    const float* Yk = Y + 4096 + h*1024;
    const float* Yv = Y + 8192 + h*1024;
    float* gout = (dir ? g_acc_h : g_acc_l) + ((size_t)(b*NC + h*16))*NPIX;

    u64 accA[16], accB[16];
    #pragma unroll
    for (int j = 0; j < 16; j++) { accA[j] = 0ULL; accB[j] = 0ULL; }
    u64 sumA2 = 0ULL, sumB2 = 0ULL;

    #pragma unroll
    for (int ch = 0; ch < 4; ch++) {
        u64 lgA[8], lgB[8];
        #pragma unroll
        for (int j = 0; j < 8; j++) { lgA[j] = 0ULL; lgB[j] = 0ULL; }

        #pragma unroll
        for (int dd = 0; dd < 16; dd++) {
            float qa = Yq[dd*64 + nA];     // pre-scaled by QS in proj weights
            float qb = Yq[dd*64 + nB];
            u64 qa2 = pk2(qa, qa);
            u64 qb2 = pk2(qb, qb);
            const ulonglong2* kr = (const ulonglong2*)(Yk + dd*64 + ch*16);
            #pragma unroll
            for (int j2 = 0; j2 < 4; j2++) {
                ulonglong2 kk = kr[j2];
                lgA[j2*2]   = fma2(qa2, kk.x, lgA[j2*2]);
                lgA[j2*2+1] = fma2(qa2, kk.y, lgA[j2*2+1]);
                lgB[j2*2]   = fma2(qb2, kk.x, lgB[j2*2]);
                lgB[j2*2+1] = fma2(qb2, kk.y, lgB[j2*2+1]);
            }
        }
        // exp (no max subtraction: logits are small; softmax is shift-invariant)
        #pragma unroll
        for (int j = 0; j < 8; j++) {
            float a, bb; upk2(a, bb, lgA[j]);
            lgA[j] = pk2(exp2f(a), exp2f(bb));
            sumA2 = add2(sumA2, lgA[j]);
            float c2, d2; upk2(c2, d2, lgB[j]);
            lgB[j] = pk2(exp2f(c2), exp2f(d2));
            sumB2 = add2(sumB2, lgB[j]);
        }
        // AV accumulate
        #pragma unroll
        for (int dd = 0; dd < 16; dd++) {
            const ulonglong2* vr = (const ulonglong2*)(Yv + dd*64 + ch*16);
            u64 aA = accA[dd], aB = accB[dd];
            #pragma unroll
            for (int j2 = 0; j2 < 4; j2++) {
                ulonglong2 vv = vr[j2];
                aA = fma2(lgA[j2*2],   vv.x, aA);
                aA = fma2(lgA[j2*2+1], vv.y, aA);
                aB = fma2(lgB[j2*2],   vv.x, aB);
                aB = fma2(lgB[j2*2+1], vv.y, aB);
            }
            accA[dd] = aA; accB[dd] = aB;
        }
    }
    float sa0, sa1, sb0, sb1;
    upk2(sa0, sa1, sumA2);
    upk2(sb0, sb1, sumB2);
    float invA = 1.f / (sa0 + sa1);
    float invB = 1.f / (sb0 + sb1);
    #pragma unroll
    for (int dd = 0; dd < 16; dd++) {
        float a, bb; upk2(a, bb, accA[dd]);
        float c, d; upk2(c, d, accB[dd]);
        atomicAdd(gout + (size_t)dd*NPIX + pixA, (a + bb) * invA);
        atomicAdd(gout + (size_t)dd*NPIX + pixB, (c + d) * invB);
    }
}

// ---------------- epilogue: normalize fold, 1x1 proj + residual ----------------
__device__ __forceinline__ int covdim(int y) {
    int imin = (y >= 8) ? ((y - 4) >> 2) : 0;
    int imax = y >> 2; if (imax > 30) imax = 30;
    return imax - imin + 1;
}

#define WST 72

__global__ void __launch_bounds__(256) epi_kernel(
    const float* __restrict__ low, const float* __restrict__ high,
    const float* __restrict__ wpl, const float* __restrict__ wph,
    float* __restrict__ out)
{
    extern __shared__ float sm[];
    float* tl = sm;                    // 8192
    float* th = sm + 8192;             // 8192
    float* wl = sm + 16384;            // 64*WST
    float* wh = sm + 16384 + 64*WST;   // 64*WST

    int t = threadIdx.x;
    int y = blockIdx.x, b = blockIdx.y;
    float cy = (float)covdim(y);

    for (int i = t; i < 8192; i += 256) {
        int c = i >> 7, x = i & 127;
        float ic = 1.f / (cy * (float)covdim(x));
        size_t gi = ((size_t)(b*NC + c)*NH + y)*NW + x;
        tl[i] = g_acc_l[gi] * ic;
        th[i] = g_acc_h[gi] * ic;
    }
    for (int i = t; i < 4096; i += 256) {
        int o = i >> 6, c = i & 63;
        wl[c*WST + o] = wpl[i];
        wh[c*WST + o] = wph[i];
    }
    __syncthreads();

    int x = t & 127, og = (t >> 7) * 32;
    u64 rl2[16], rh2[16];
    #pragma unroll
    for (int j = 0; j < 16; j++) { rl2[j] = 0ULL; rh2[j] = 0ULL; }

    for (int c = 0; c < 64; c++) {
        float tv = tl[c*128 + x];
        float hv = th[c*128 + x];
        u64 tv2 = pk2(tv, tv);
        u64 hv2 = pk2(hv, hv);
        const ulonglong2* wlr = (const ulonglong2*)(wl + c*WST + og);
        const ulonglong2* whr = (const ulonglong2*)(wh + c*WST + og);
        #pragma unroll
        for (int o4 = 0; o4 < 8; o4++) {
            ulonglong2 a2 = wlr[o4];
            ulonglong2 b2 = whr[o4];
            rl2[o4*2]   = fma2(tv2, a2.x, rl2[o4*2]);
            rl2[o4*2+1] = fma2(tv2, a2.y, rl2[o4*2+1]);
            rh2[o4*2]   = fma2(hv2, b2.x, rh2[o4*2]);
            rh2[o4*2+1] = fma2(hv2, b2.y, rh2[o4*2+1]);
        }
    }
    size_t half = (size_t)NB*NC*NPIX;
    #pragma unroll
    for (int j = 0; j < 16; j++) {
        float a, bb; upk2(a, bb, rl2[j]);
        float c2, d2; upk2(c2, d2, rh2[j]);
        int o0 = og + j*2;
        size_t gi0 = ((size_t)(b*NC + o0)*NH + y)*NW + x;
        size_t gi1 = ((size_t)(b*NC + o0 + 1)*NH + y)*NW + x;
        out[gi0]        = low[gi0]  + a;
        out[gi1]        = low[gi1]  + bb;
        out[half + gi0] = high[gi0] + c2;
        out[half + gi1] = high[gi1] + d2;
    }
}

extern "C" void kernel_launch(void* const* d_in, const int* in_sizes, int n_in,
                              void* d_out, int out_size)
{
    (void)in_sizes; (void)n_in; (void)out_size;
    const float* low  = (const float*)d_in[0];
    const float* high = (const float*)d_in[1];
    const float* w_ql = (const float*)d_in[2];
    const float* w_kh = (const float*)d_in[3];
    const float* w_vh = (const float*)d_in[4];
    const float* w_qh = (const float*)d_in[5];
    const float* w_kl = (const float*)d_in[6];
    const float* w_vl = (const float*)d_in[7];
    const float* wpl  = (const float*)d_in[8];
    const float* wph  = (const float*)d_in[9];

    void* pl; cudaGetSymbolAddress(&pl, g_acc_l);
    void* ph; cudaGetSymbolAddress(&ph, g_acc_h);
    cudaMemsetAsync(pl, 0, sizeof(float)*(size_t)NB*NC*NPIX);
    cudaMemsetAsync(ph, 0, sizeof(float)*(size_t)NB*NC*NPIX);

    cudaFuncSetAttribute(proj_kernel, cudaFuncAttributeMaxDynamicSharedMemorySize, (8192+13056)*4);
    cudaFuncSetAttribute(attn_kernel, cudaFuncAttributeMaxDynamicSharedMemorySize, 12288*4);
    cudaFuncSetAttribute(epi_kernel,  cudaFuncAttributeMaxDynamicSharedMemorySize, (16384 + 2*64*WST)*4);

    mean_kernel<<<NB*NC, 256>>>(high);
    se_kernel<<<1, 256>>>((const float*)d_in[10], (const float*)d_in[11],
                          (const float*)d_in[12], (const float*)d_in[13],
                          (const float*)d_in[14], (const float*)d_in[15]);
    proj_kernel<<<dim3(NPIX/64, NB), 256, (8192+13056)*4>>>(low, high, w_ql, w_kh, w_vh, w_qh, w_kl, w_vl);
    attn_kernel<<<dim3(NL, 2, NB), 128, 12288*4>>>();
    epi_kernel<<<dim3(NH, NB), 256, (16384 + 2*64*WST)*4>>>(low, high, wpl, wph, (float*)d_out);
}

// round 6
// speedup vs baseline: 2.2853x; 1.0007x over previous
#include <cuda_runtime.h>

#define NB 4
#define NC 64
#define NH 128
#define NW 128
#define NPIX (NH*NW)
#define NWIN 31
#define NL (NWIN*NWIN)

typedef unsigned long long u64;

// proj slot order: 0=ql 1=kh 2=vh 3=qh 4=kl 5=vl  (dir0 uses 0,1,2; dir1 uses 3,4,5)
__device__ float g_proj[6*NB*NC*NPIX];
__device__ float g_acc_l[NB*NC*NPIX];
__device__ float g_acc_h[NB*NC*NPIX];
__device__ float g_mean[NB*NC];
__device__ float g_sgate[NB*NC];

// ---------------- packed f32x2 helpers ----------------
__device__ __forceinline__ u64 pk2(float lo, float hi) {
    u64 r;
    asm("mov.b64 %0,{%1,%2};" : "=l"(r) : "f"(lo), "f"(hi));
    return r;
}
__device__ __forceinline__ void upk2(float& lo, float& hi, u64 v) {
    asm("mov.b64 {%0,%1},%2;" : "=f"(lo), "=f"(hi) : "l"(v));
}
__device__ __forceinline__ u64 fma2(u64 a, u64 b, u64 c) {
    u64 d;
    asm("fma.rn.f32x2 %0,%1,%2,%3;" : "=l"(d) : "l"(a), "l"(b), "l"(c));
    return d;
}
__device__ __forceinline__ u64 add2(u64 a, u64 b) {
    u64 d;
    asm("add.rn.f32x2 %0,%1,%2;" : "=l"(d) : "l"(a), "l"(b));
    return d;
}

// ---------------- SE: per-channel global mean ----------------
__global__ void mean_kernel(const float* __restrict__ high) {
    int bc = blockIdx.x;
    const float* p = high + (size_t)bc * NPIX;
    float s = 0.f;
    for (int i = threadIdx.x; i < NPIX; i += 256) s += p[i];
    __shared__ float red[256];
    red[threadIdx.x] = s; __syncthreads();
    for (int k = 128; k > 0; k >>= 1) {
        if (threadIdx.x < k) red[threadIdx.x] += red[threadIdx.x + k];
        __syncthreads();
    }
    if (threadIdx.x == 0) g_mean[bc] = red[0] * (1.f/NPIX);
}

// ---------------- SE: gate per (b,c) ----------------
__global__ void se_kernel(const float* __restrict__ w10, const float* __restrict__ w20,
                          const float* __restrict__ w11, const float* __restrict__ w21,
                          const float* __restrict__ w12, const float* __restrict__ w22) {
    int t = threadIdx.x;
    int b = t >> 6, c = t & 63;
    int g  = (c < 22) ? 0 : ((c < 43) ? 1 : 2);
    int of = (g == 0) ? 0 : ((g == 1) ? 22 : 43);
    int gc = (g == 0) ? 22 : 21;
    const float* w1 = (g==0) ? w10 : ((g==1) ? w11 : w12);
    const float* w2 = (g==0) ? w20 : ((g==1) ? w21 : w22);
    float h = 0.f;
    for (int j = 0; j < gc; j++) h += g_mean[b*64 + of + j] * w1[j];
    h = fmaxf(h, 0.f);
    float v = h * w2[c - of];
    g_sgate[t] = 1.f / (1.f + __expf(-v));
}

// ---------------- global projections (fma2; q-weights pre-scaled by 0.25*log2e) ----------------
#define WTS 68
#define QS 0.36067376022224085f
__global__ void __launch_bounds__(256,2) proj_kernel(
    const float* __restrict__ low, const float* __restrict__ high,
    const float* __restrict__ w_ql, const float* __restrict__ w_kh,
    const float* __restrict__ w_vh, const float* __restrict__ w_qh,
    const float* __restrict__ w_kl, const float* __restrict__ w_vl)
{
    extern __shared__ float sm[];
    float* xl = sm;            // 4096
    float* xh = sm + 4096;     // 4096
    float* wt = sm + 8192;     // 3 * 64*68

    int t = threadIdx.x;
    int pix0 = blockIdx.x * 64;
    int b = blockIdx.y;

    for (int i4 = t; i4 < 1024; i4 += 256) {
        int c = i4 >> 4, pp = (i4 & 15) * 4;
        size_t gi = (size_t)(b*NC + c)*NPIX + pix0 + pp;
        float4 vl = *(const float4*)(low + gi);
        float4 vh = *(const float4*)(high + gi);
        float gt = g_sgate[b*64 + c];
        vh.x *= gt; vh.y *= gt; vh.z *= gt; vh.w *= gt;
        *(float4*)(xl + c*64 + pp) = vl;
        *(float4*)(xh + c*64 + pp) = vh;
    }

    int ot = (t >> 4) << 2;
    int nb = (t & 15) << 2;

    for (int g = 0; g < 2; g++) {
        __syncthreads();
        const float* W0 = g ? w_kh : w_ql;
        const float* W1 = g ? w_vh : w_kl;
        const float* W2 = g ? w_qh : w_vl;
        for (int i = t; i < 12288; i += 256) {
            int p = i >> 12, j = i & 4095;
            int o = j >> 6, c = j & 63;
            const float* Wp = (p == 0) ? W0 : ((p == 1) ? W1 : W2);
            float wv = Wp[j];
            // fold attention scale into q-projection weights (slot0 / slot3)
            if ((g == 0 && p == 0) || (g == 1 && p == 2)) wv *= QS;
            wt[p*4352 + c*WTS + o] = wv;
        }
        __syncthreads();
        const float* Xs = g ? xh : xl;

        u64 acc2[3][4][2];
        #pragma unroll
        for (int p = 0; p < 3; p++)
            #pragma unroll
            for (int n = 0; n < 4; n++) { acc2[p][n][0] = 0ULL; acc2[p][n][1] = 0ULL; }

        #pragma unroll 2
        for (int c0 = 0; c0 < 64; c0 += 4) {
            #pragma unroll
            for (int k = 0; k < 4; k++) {
                float4 x4 = *(const float4*)(Xs + (c0+k)*64 + nb);
                u64 xd0 = pk2(x4.x, x4.x);
                u64 xd1 = pk2(x4.y, x4.y);
                u64 xd2 = pk2(x4.z, x4.z);
                u64 xd3 = pk2(x4.w, x4.w);
                #pragma unroll
                for (int p = 0; p < 3; p++) {
                    ulonglong2 w2v = *(const ulonglong2*)(wt + p*4352 + (c0+k)*WTS + ot);
                    acc2[p][0][0] = fma2(xd0, w2v.x, acc2[p][0][0]);
                    acc2[p][0][1] = fma2(xd0, w2v.y, acc2[p][0][1]);
                    acc2[p][1][0] = fma2(xd1, w2v.x, acc2[p][1][0]);
                    acc2[p][1][1] = fma2(xd1, w2v.y, acc2[p][1][1]);
                    acc2[p][2][0] = fma2(xd2, w2v.x, acc2[p][2][0]);
                    acc2[p][2][1] = fma2(xd2, w2v.y, acc2[p][2][1]);
                    acc2[p][3][0] = fma2(xd3, w2v.x, acc2[p][3][0]);
                    acc2[p][3][1] = fma2(xd3, w2v.y, acc2[p][3][1]);
                }
            }
        }
        int slots[3];
        slots[0] = g ? 1 : 0; slots[1] = g ? 2 : 4; slots[2] = g ? 3 : 5;
        #pragma unroll
        for (int p = 0; p < 3; p++) {
            float lo0[4], hi0[4], lo1[4], hi1[4];
            #pragma unroll
            for (int n = 0; n < 4; n++) {
                upk2(lo0[n], hi0[n], acc2[p][n][0]);
                upk2(lo1[n], hi1[n], acc2[p][n][1]);
            }
            size_t base = (size_t)slots[p]*NB*NC*NPIX + (size_t)(b*NC)*NPIX + pix0 + nb;
            *(float4*)(g_proj + base + (size_t)(ot+0)*NPIX) = make_float4(lo0[0],lo0[1],lo0[2],lo0[3]);
            *(float4*)(g_proj + base + (size_t)(ot+1)*NPIX) = make_float4(hi0[0],hi0[1],hi0[2],hi0[3]);
            *(float4*)(g_proj + base + (size_t)(ot+2)*NPIX) = make_float4(lo1[0],lo1[1],lo1[2],lo1[3]);
            *(float4*)(g_proj + base + (size_t)(ot+3)*NPIX) = make_float4(hi1[0],hi1[1],hi1[2],hi1[3]);
        }
    }
}

// ---------------- attention: one (window, dir, batch) per block; 48KB smem ----------------
__global__ void __launch_bounds__(128, 4) attn_kernel()
{
    extern __shared__ float Y[];  // q[4096] k[4096] v[4096]

    int t = threadIdx.x;
    int l = blockIdx.x, dir = blockIdx.y, b = blockIdx.z;
    int y0 = (l / NWIN) * 4, x0 = (l % NWIN) * 4;

    // stage this direction's 3 tiles (slots dir*3 + {0,1,2})
    for (int i4 = t; i4 < 3072; i4 += 128) {
        int p = i4 >> 10, rem = i4 & 1023;
        int slot = dir*3 + p;
        int c = rem >> 4, q4 = rem & 15;
        int r = q4 >> 1, cc = (q4 & 1) * 4;
        size_t gi = ((size_t)slot*NB*NC + (size_t)(b*NC + c))*NPIX + (size_t)(y0 + r)*NW + x0 + cc;
        *(float4*)(Y + p*4096 + c*64 + r*8 + cc) = *(const float4*)(g_proj + gi);
    }
    __syncthreads();

    int h = t >> 5, lane = t & 31;
    int nA = lane, nB = lane + 32;
    size_t pixA = (size_t)(y0 + (nA >> 3))*NW + x0 + (nA & 7);
    size_t pixB = (size_t)(y0 + (nB >> 3))*NW + x0 + (nB & 7);

    const float* Yq = Y + h*1024;
    const float* Yk = Y + 4096 + h*1024;
    const float* Yv = Y + 8192 + h*1024;
    float* gout = (dir ? g_acc_h : g_acc_l) + ((size_t)(b*NC + h*16))*NPIX;

    u64 accA[16], accB[16];
    #pragma unroll
    for (int j = 0; j < 16; j++) { accA[j] = 0ULL; accB[j] = 0ULL; }
    u64 sumA2 = 0ULL, sumB2 = 0ULL;

    #pragma unroll
    for (int ch = 0; ch < 4; ch++) {
        u64 lgA[8], lgB[8];
        #pragma unroll
        for (int j = 0; j < 8; j++) { lgA[j] = 0ULL; lgB[j] = 0ULL; }

        #pragma unroll
        for (int dd = 0; dd < 16; dd++) {
            float qa = Yq[dd*64 + nA];     // pre-scaled by QS in proj weights
            float qb = Yq[dd*64 + nB];
            u64 qa2 = pk2(qa, qa);
            u64 qb2 = pk2(qb, qb);
            const ulonglong2* kr = (const ulonglong2*)(Yk + dd*64 + ch*16);
            #pragma unroll
            for (int j2 = 0; j2 < 4; j2++) {
                ulonglong2 kk = kr[j2];
                lgA[j2*2]   = fma2(qa2, kk.x, lgA[j2*2]);
                lgA[j2*2+1] = fma2(qa2, kk.y, lgA[j2*2+1]);
                lgB[j2*2]   = fma2(qb2, kk.x, lgB[j2*2]);
                lgB[j2*2+1] = fma2(qb2, kk.y, lgB[j2*2+1]);
            }
        }
        // exp (no max subtraction: logits are small; softmax is shift-invariant)
        #pragma unroll
        for (int j = 0; j < 8; j++) {
            float a, bb; upk2(a, bb, lgA[j]);
            lgA[j] = pk2(exp2f(a), exp2f(bb));
            sumA2 = add2(sumA2, lgA[j]);
            float c2, d2; upk2(c2, d2, lgB[j]);
            lgB[j] = pk2(exp2f(c2), exp2f(d2));
            sumB2 = add2(sumB2, lgB[j]);
        }
        // AV accumulate
        #pragma unroll
        for (int dd = 0; dd < 16; dd++) {
            const ulonglong2* vr = (const ulonglong2*)(Yv + dd*64 + ch*16);
            u64 aA = accA[dd], aB = accB[dd];
            #pragma unroll
            for (int j2 = 0; j2 < 4; j2++) {
                ulonglong2 vv = vr[j2];
                aA = fma2(lgA[j2*2],   vv.x, aA);
                aA = fma2(lgA[j2*2+1], vv.y, aA);
                aB = fma2(lgB[j2*2],   vv.x, aB);
                aB = fma2(lgB[j2*2+1], vv.y, aB);
            }
            accA[dd] = aA; accB[dd] = aB;
        }
    }
    float sa0, sa1, sb0, sb1;
    upk2(sa0, sa1, sumA2);
    upk2(sb0, sb1, sumB2);
    float invA = 1.f / (sa0 + sa1);
    float invB = 1.f / (sb0 + sb1);
    #pragma unroll
    for (int dd = 0; dd < 16; dd++) {
        float a, bb; upk2(a, bb, accA[dd]);
        float c, d; upk2(c, d, accB[dd]);
        atomicAdd(gout + (size_t)dd*NPIX + pixA, (a + bb) * invA);
        atomicAdd(gout + (size_t)dd*NPIX + pixB, (c + d) * invB);
    }
}

// ---------------- epilogue: normalize fold, 1x1 proj + residual ----------------
__device__ __forceinline__ int covdim(int y) {
    int imin = (y >= 8) ? ((y - 4) >> 2) : 0;
    int imax = y >> 2; if (imax > 30) imax = 30;
    return imax - imin + 1;
}

#define WST 72

__global__ void __launch_bounds__(256) epi_kernel(
    const float* __restrict__ low, const float* __restrict__ high,
    const float* __restrict__ wpl, const float* __restrict__ wph,
    float* __restrict__ out)
{
    extern __shared__ float sm[];
    float* tl = sm;                    // 8192
    float* th = sm + 8192;             // 8192
    float* wl = sm + 16384;            // 64*WST
    float* wh = sm + 16384 + 64*WST;   // 64*WST

    int t = threadIdx.x;
    int y = blockIdx.x, b = blockIdx.y;
    float cy = (float)covdim(y);

    for (int i = t; i < 8192; i += 256) {
        int c = i >> 7, x = i & 127;
        float ic = 1.f / (cy * (float)covdim(x));
        size_t gi = ((size_t)(b*NC + c)*NH + y)*NW + x;
        tl[i] = g_acc_l[gi] * ic;
        th[i] = g_acc_h[gi] * ic;
    }
    for (int i = t; i < 4096; i += 256) {
        int o = i >> 6, c = i & 63;
        wl[c*WST + o] = wpl[i];
        wh[c*WST + o] = wph[i];
    }
    __syncthreads();

    int x = t & 127, og = (t >> 7) * 32;
    u64 rl2[16], rh2[16];
    #pragma unroll
    for (int j = 0; j < 16; j++) { rl2[j] = 0ULL; rh2[j] = 0ULL; }

    for (int c = 0; c < 64; c++) {
        float tv = tl[c*128 + x];
        float hv = th[c*128 + x];
        u64 tv2 = pk2(tv, tv);
        u64 hv2 = pk2(hv, hv);
        const ulonglong2* wlr = (const ulonglong2*)(wl + c*WST + og);
        const ulonglong2* whr = (const ulonglong2*)(wh + c*WST + og);
        #pragma unroll
        for (int o4 = 0; o4 < 8; o4++) {
            ulonglong2 a2 = wlr[o4];
            ulonglong2 b2 = whr[o4];
            rl2[o4*2]   = fma2(tv2, a2.x, rl2[o4*2]);
            rl2[o4*2+1] = fma2(tv2, a2.y, rl2[o4*2+1]);
            rh2[o4*2]   = fma2(hv2, b2.x, rh2[o4*2]);
            rh2[o4*2+1] = fma2(hv2, b2.y, rh2[o4*2+1]);
        }
    }
    size_t half = (size_t)NB*NC*NPIX;
    #pragma unroll
    for (int j = 0; j < 16; j++) {
        float a, bb; upk2(a, bb, rl2[j]);
        float c2, d2; upk2(c2, d2, rh2[j]);
        int o0 = og + j*2;
        size_t gi0 = ((size_t)(b*NC + o0)*NH + y)*NW + x;
        size_t gi1 = ((size_t)(b*NC + o0 + 1)*NH + y)*NW + x;
        out[gi0]        = low[gi0]  + a;
        out[gi1]        = low[gi1]  + bb;
        out[half + gi0] = high[gi0] + c2;
        out[half + gi1] = high[gi1] + d2;
    }
}

extern "C" void kernel_launch(void* const* d_in, const int* in_sizes, int n_in,
                              void* d_out, int out_size)
{
    (void)in_sizes; (void)n_in; (void)out_size;
    const float* low  = (const float*)d_in[0];
    const float* high = (const float*)d_in[1];
    const float* w_ql = (const float*)d_in[2];
    const float* w_kh = (const float*)d_in[3];
    const float* w_vh = (const float*)d_in[4];
    const float* w_qh = (const float*)d_in[5];
    const float* w_kl = (const float*)d_in[6];
    const float* w_vl = (const float*)d_in[7];
    const float* wpl  = (const float*)d_in[8];
    const float* wph  = (const float*)d_in[9];

    void* pl; cudaGetSymbolAddress(&pl, g_acc_l);
    void* ph; cudaGetSymbolAddress(&ph, g_acc_h);
    cudaMemsetAsync(pl, 0, sizeof(float)*(size_t)NB*NC*NPIX);
    cudaMemsetAsync(ph, 0, sizeof(float)*(size_t)NB*NC*NPIX);

    cudaFuncSetAttribute(proj_kernel, cudaFuncAttributeMaxDynamicSharedMemorySize, (8192+13056)*4);
    cudaFuncSetAttribute(attn_kernel, cudaFuncAttributeMaxDynamicSharedMemorySize, 12288*4);
    cudaFuncSetAttribute(epi_kernel,  cudaFuncAttributeMaxDynamicSharedMemorySize, (16384 + 2*64*WST)*4);

    mean_kernel<<<NB*NC, 256>>>(high);
    se_kernel<<<1, 256>>>((const float*)d_in[10], (const float*)d_in[11],
                          (const float*)d_in[12], (const float*)d_in[13],
                          (const float*)d_in[14], (const float*)d_in[15]);
    proj_kernel<<<dim3(NPIX/64, NB), 256, (8192+13056)*4>>>(low, high, w_ql, w_kh, w_vh, w_qh, w_kl, w_vl);
    attn_kernel<<<dim3(NL, 2, NB), 128, 12288*4>>>();
    epi_kernel<<<dim3(NH, NB), 256, (16384 + 2*64*WST)*4>>>(low, high, wpl, wph, (float*)d_out);
}